// round 1
// baseline (speedup 1.0000x reference)
#include <cuda_runtime.h>
#include <math.h>

// Problem constants
#define BATCHN 2
#define LEN    2048
#define DM     1024
#define DI     2048
#define DS     16
#define MTOK   (BATCHN*LEN)      // 4096 tokens
#define PROJW  (DI + 2*DS)       // 2080

// ---------------- scratch (device globals; no allocation allowed) ----------------
__device__ float g_xz  [(size_t)MTOK * 2*DI];   // 64 MB  in_proj output [xs | z]
__device__ float g_u   [(size_t)MTOK * DI];     // 32 MB  conv+silu output
__device__ float g_proj[(size_t)MTOK * PROJW];  // 34 MB  x_proj output [d_in | B | C]
__device__ float g_dlt [(size_t)MTOK * DI];     // 32 MB  softplus(dt)
__device__ float g_yg  [(size_t)MTOK * DI];     // 32 MB  scan output * silu(z)

// ---------------- SGEMM: C[M,N] = A[M,K] * B[N,K]^T (+ epilogue) ----------------
// MODE 0: plain store
// MODE 1: v += bias[n]; v = softplus(v)
// MODE 2: v += resid[m,n]
template<int MODE>
__global__ __launch_bounds__(256)
void sgemm_tn(const float* __restrict__ A, int lda,
              const float* __restrict__ B, int ldb,
              float* __restrict__ C, int ldc,
              int M, int N, int K,
              const float* __restrict__ bias,
              const float* __restrict__ resid, int ldr)
{
    __shared__ float As[8][128];
    __shared__ float Bs[8][128];

    const int tid = threadIdx.x;
    const int m0 = blockIdx.y * 128;
    const int n0 = blockIdx.x * 128;
    const int tx = tid & 15;         // 16 cols of threads
    const int ty = tid >> 4;         // 16 rows of threads

    float acc[8][8];
#pragma unroll
    for (int i = 0; i < 8; i++)
#pragma unroll
        for (int j = 0; j < 8; j++) acc[i][j] = 0.f;

    const int lrow = tid >> 1;        // 0..127
    const int lcol = (tid & 1) * 4;   // 0 or 4
    const float* Aptr = A + (size_t)(m0 + lrow) * lda + lcol;
    const bool   bok  = (n0 + lrow) < N;
    const float* Bptr = B + (size_t)(n0 + lrow) * ldb + lcol;

    for (int k0 = 0; k0 < K; k0 += 8) {
        float4 av = *(const float4*)(Aptr + k0);
        float4 bv = bok ? *(const float4*)(Bptr + k0) : make_float4(0.f, 0.f, 0.f, 0.f);
        As[lcol + 0][lrow] = av.x; As[lcol + 1][lrow] = av.y;
        As[lcol + 2][lrow] = av.z; As[lcol + 3][lrow] = av.w;
        Bs[lcol + 0][lrow] = bv.x; Bs[lcol + 1][lrow] = bv.y;
        Bs[lcol + 2][lrow] = bv.z; Bs[lcol + 3][lrow] = bv.w;
        __syncthreads();

#pragma unroll
        for (int kk = 0; kk < 8; kk++) {
            float4 a0 = *(const float4*)&As[kk][ty * 8];
            float4 a1 = *(const float4*)&As[kk][ty * 8 + 4];
            float4 b0 = *(const float4*)&Bs[kk][tx * 8];
            float4 b1 = *(const float4*)&Bs[kk][tx * 8 + 4];
            float af[8] = {a0.x, a0.y, a0.z, a0.w, a1.x, a1.y, a1.z, a1.w};
            float bf[8] = {b0.x, b0.y, b0.z, b0.w, b1.x, b1.y, b1.z, b1.w};
#pragma unroll
            for (int i = 0; i < 8; i++)
#pragma unroll
                for (int j = 0; j < 8; j++)
                    acc[i][j] = fmaf(af[i], bf[j], acc[i][j]);
        }
        __syncthreads();
    }

#pragma unroll
    for (int i = 0; i < 8; i++) {
        const int m = m0 + ty * 8 + i;
#pragma unroll
        for (int j = 0; j < 8; j++) {
            const int n = n0 + tx * 8 + j;
            if (n < N) {
                float v = acc[i][j];
                if (MODE == 1) {
                    v += bias[n];
                    v = (v > 20.f) ? v : log1pf(expf(v));   // softplus
                }
                if (MODE == 2) {
                    v += resid[(size_t)m * ldr + n];
                }
                C[(size_t)m * ldc + n] = v;
            }
        }
    }
}

// ---------------- depthwise causal conv1d (k=4) + SiLU ----------------
__global__ void conv_silu_kernel(const float* __restrict__ cw,
                                 const float* __restrict__ cb)
{
    const size_t idx = (size_t)blockIdx.x * blockDim.x + threadIdx.x;
    if (idx >= (size_t)MTOK * DI) return;
    const int d = (int)(idx % DI);
    const int m = (int)(idx / DI);    // b*LEN + t
    const int t = m % LEN;

    const float w0 = cw[d * 4 + 0], w1 = cw[d * 4 + 1];
    const float w2 = cw[d * 4 + 2], w3 = cw[d * 4 + 3];
    float acc = cb[d];
    if (t >= 3) acc = fmaf(g_xz[(size_t)(m - 3) * (2 * DI) + d], w0, acc);
    if (t >= 2) acc = fmaf(g_xz[(size_t)(m - 2) * (2 * DI) + d], w1, acc);
    if (t >= 1) acc = fmaf(g_xz[(size_t)(m - 1) * (2 * DI) + d], w2, acc);
    acc = fmaf(g_xz[(size_t)m * (2 * DI) + d], w3, acc);
    const float sg = 1.f / (1.f + expf(-acc));
    g_u[idx] = acc * sg;
}

// ---------------- selective scan + skip + gate ----------------
// Layout: 16 lanes = 16 states of one channel; warp handles 2 channels.
// Block = 256 threads = 16 channels. Grid = BATCHN * (DI/16) = 256 blocks.
__global__ __launch_bounds__(256)
void scan_kernel(const float* __restrict__ A_log,
                 const float* __restrict__ Dp)
{
    const int tid  = threadIdx.x;
    const int wid  = tid >> 5;
    const int lane = tid & 31;
    const int half = lane >> 4;        // which channel within warp
    const int n    = lane & 15;        // state index

    const int blocks_per_batch = DI / 16;   // 128
    const int b      = blockIdx.x / blocks_per_batch;
    const int dchunk = blockIdx.x % blocks_per_batch;
    const int d      = dchunk * 16 + wid * 2 + half;

    const float a_coef = -expf(A_log[d * DS + n]);
    const float Dd     = Dp[d];
    float s = 0.f;

    const int mbase = b * LEN;
    for (int t = 0; t < LEN; t++) {
        const int m = mbase + t;
        const float dt = g_dlt[(size_t)m * DI + d];
        const float uu = g_u  [(size_t)m * DI + d];
        const float Bv = g_proj[(size_t)m * PROJW + DI + n];
        const float Cv = g_proj[(size_t)m * PROJW + DI + DS + n];

        const float dA = __expf(dt * a_coef);
        s = fmaf(s, dA, dt * Bv * uu);

        float p = s * Cv;
        p += __shfl_xor_sync(0xffffffffu, p, 8);
        p += __shfl_xor_sync(0xffffffffu, p, 4);
        p += __shfl_xor_sync(0xffffffffu, p, 2);
        p += __shfl_xor_sync(0xffffffffu, p, 1);

        if (n == 0) {
            const float zz = g_xz[(size_t)m * (2 * DI) + DI + d];
            const float y  = p + uu * Dd;
            const float sz = zz / (1.f + __expf(-zz));   // silu(z)
            g_yg[(size_t)m * DI + d] = y * sz;
        }
    }
}

// ---------------- LayerNorm over last dim (1024), in-place on d_out ----------------
__global__ __launch_bounds__(256)
void layernorm_kernel(float* __restrict__ out,
                      const float* __restrict__ g,
                      const float* __restrict__ bta)
{
    const int m = blockIdx.x;
    const int tid = threadIdx.x;
    float* row = out + (size_t)m * DM;

    float4 v = ((const float4*)row)[tid];           // 256 * 4 = 1024
    const float4 gg = ((const float4*)g)[tid];
    const float4 bb = ((const float4*)bta)[tid];

    __shared__ float sh[8];
    __shared__ float bc;

    // sum -> mean
    float sv = v.x + v.y + v.z + v.w;
    for (int o = 16; o > 0; o >>= 1) sv += __shfl_xor_sync(0xffffffffu, sv, o);
    if ((tid & 31) == 0) sh[tid >> 5] = sv;
    __syncthreads();
    if (tid < 32) {
        float t2 = (tid < 8) ? sh[tid] : 0.f;
        for (int o = 4; o > 0; o >>= 1) t2 += __shfl_xor_sync(0xffffffffu, t2, o);
        if (tid == 0) bc = t2;
    }
    __syncthreads();
    const float mu = bc * (1.f / DM);
    __syncthreads();

    // sumsq(x - mu) -> var
    float dx0 = v.x - mu, dx1 = v.y - mu, dx2 = v.z - mu, dx3 = v.w - mu;
    float sq = dx0 * dx0 + dx1 * dx1 + dx2 * dx2 + dx3 * dx3;
    for (int o = 16; o > 0; o >>= 1) sq += __shfl_xor_sync(0xffffffffu, sq, o);
    if ((tid & 31) == 0) sh[tid >> 5] = sq;
    __syncthreads();
    if (tid < 32) {
        float t2 = (tid < 8) ? sh[tid] : 0.f;
        for (int o = 4; o > 0; o >>= 1) t2 += __shfl_xor_sync(0xffffffffu, t2, o);
        if (tid == 0) bc = t2;
    }
    __syncthreads();
    const float var = bc * (1.f / DM);
    const float inv = rsqrtf(var + 1e-5f);

    v.x = dx0 * inv * gg.x + bb.x;
    v.y = dx1 * inv * gg.y + bb.y;
    v.z = dx2 * inv * gg.z + bb.z;
    v.w = dx3 * inv * gg.w + bb.w;
    ((float4*)row)[tid] = v;
}

// ---------------- host launch ----------------
extern "C" void kernel_launch(void* const* d_in, const int* in_sizes, int n_in,
                              void* d_out, int out_size)
{
    const float* x      = (const float*)d_in[0];
    const float* W_in   = (const float*)d_in[1];
    const float* conv_w = (const float*)d_in[2];
    const float* conv_b = (const float*)d_in[3];
    const float* W_x    = (const float*)d_in[4];
    const float* W_dt   = (const float*)d_in[5];
    const float* b_dt   = (const float*)d_in[6];
    const float* A_log  = (const float*)d_in[7];
    const float* Dp     = (const float*)d_in[8];
    const float* W_out  = (const float*)d_in[9];
    const float* ln_g   = (const float*)d_in[10];
    const float* ln_b   = (const float*)d_in[11];
    float* out = (float*)d_out;

    float *xz, *u, *proj, *dlt, *yg;
    cudaGetSymbolAddress((void**)&xz,   g_xz);
    cudaGetSymbolAddress((void**)&u,    g_u);
    cudaGetSymbolAddress((void**)&proj, g_proj);
    cudaGetSymbolAddress((void**)&dlt,  g_dlt);
    cudaGetSymbolAddress((void**)&yg,   g_yg);

    dim3 thr(256);

    // 1) xz = x @ W_in^T                (4096 x 4096, K=1024)
    sgemm_tn<0><<<dim3(32, 32), thr>>>(x, DM, W_in, DM, xz, 2 * DI,
                                       MTOK, 2 * DI, DM, nullptr, nullptr, 0);

    // 2) u = silu(causal_conv(xs) + cb)
    conv_silu_kernel<<<(unsigned)(((size_t)MTOK * DI + 255) / 256), thr>>>(conv_w, conv_b);

    // 3) proj = u @ W_x^T               (4096 x 2080, K=2048)
    sgemm_tn<0><<<dim3(17, 32), thr>>>(u, DI, W_x, DI, proj, PROJW,
                                       MTOK, PROJW, DI, nullptr, nullptr, 0);

    // 4) delta = softplus(proj[:, :2048] @ W_dt^T + b_dt)
    sgemm_tn<1><<<dim3(16, 32), thr>>>(proj, PROJW, W_dt, DI, dlt, DI,
                                       MTOK, DI, DI, b_dt, nullptr, 0);

    // 5) selective scan + skip + gate -> yg
    scan_kernel<<<BATCHN * (DI / 16), thr>>>(A_log, Dp);

    // 6) out = yg @ W_out^T + x          (4096 x 1024, K=2048)
    sgemm_tn<2><<<dim3(8, 32), thr>>>(yg, DI, W_out, DI, out, DM,
                                      MTOK, DM, DI, nullptr, x, DM);

    // 7) layernorm in place
    layernorm_kernel<<<MTOK, thr>>>(out, ln_g, ln_b);
}

// round 6
// speedup vs baseline: 1.4939x; 1.4939x over previous
#include <cuda_runtime.h>
#include <cuda_bf16.h>
#include <math.h>
#include <cstdint>

// Problem constants
#define BATCHN 2
#define LEN    2048
#define DM     1024
#define DI     2048
#define DS     16
#define MTOK   (BATCHN*LEN)      // 4096 tokens
#define PROJW  (DI + 2*DS)       // 2080

__device__ __forceinline__ uint32_t smem_to_u32(const void* p) {
    uint32_t a;
    asm("{ .reg .u64 t; cvta.to.shared.u64 t, %1; cvt.u32.u64 %0, t; }" : "=r"(a) : "l"(p));
    return a;
}
#define SMEM_SWIZZLE_128B(byte_offset) \
    ((byte_offset) ^ (((byte_offset) >> 3) & 0x70))

#define LDMATRIX_X4(r0, r1, r2, r3, addr) \
    asm volatile("ldmatrix.sync.aligned.m8n8.x4.shared.b16 {%0,%1,%2,%3}, [%4];" \
        : "=r"(r0), "=r"(r1), "=r"(r2), "=r"(r3) : "r"(addr))
#define LDMATRIX_X2(r0, r1, addr) \
    asm volatile("ldmatrix.sync.aligned.m8n8.x2.shared.b16 {%0,%1}, [%2];" \
        : "=r"(r0), "=r"(r1) : "r"(addr))
#define MMA16816(d, a, b) \
    asm volatile("mma.sync.aligned.m16n8k16.row.col.f32.bf16.bf16.f32 " \
        "{%0,%1,%2,%3}, {%4,%5,%6,%7}, {%8,%9}, {%0,%1,%2,%3};" \
        : "+f"((d)[0]), "+f"((d)[1]), "+f"((d)[2]), "+f"((d)[3]) \
        : "r"((a)[0]), "r"((a)[1]), "r"((a)[2]), "r"((a)[3]), \
          "r"((b)[0]), "r"((b)[1]))

// ---------------- scratch (device globals; no allocation allowed) ----------------
__device__ float g_xz  [(size_t)MTOK * 2*DI];   // in_proj output [xs | z]
__device__ float g_u   [(size_t)MTOK * DI];     // conv+silu output
__device__ float g_proj[(size_t)MTOK * PROJW];  // x_proj output [d_in | B | C]
__device__ float g_dlt [(size_t)MTOK * DI];     // softplus(dt)
__device__ float g_yg  [(size_t)MTOK * DI];     // scan output * silu(z)

// bf16 hi/lo split operand buffers
__device__ __nv_bfloat16 g_x_h  [(size_t)MTOK * DM];
__device__ __nv_bfloat16 g_x_l  [(size_t)MTOK * DM];
__device__ __nv_bfloat16 g_Wi_h [(size_t)2*DI * DM];
__device__ __nv_bfloat16 g_Wi_l [(size_t)2*DI * DM];
__device__ __nv_bfloat16 g_u_h  [(size_t)MTOK * DI];
__device__ __nv_bfloat16 g_u_l  [(size_t)MTOK * DI];
__device__ __nv_bfloat16 g_Wx_h [(size_t)PROJW * DI];
__device__ __nv_bfloat16 g_Wx_l [(size_t)PROJW * DI];
__device__ __nv_bfloat16 g_di_h [(size_t)MTOK * DI];
__device__ __nv_bfloat16 g_di_l [(size_t)MTOK * DI];
__device__ __nv_bfloat16 g_Wd_h [(size_t)DI * DI];
__device__ __nv_bfloat16 g_Wd_l [(size_t)DI * DI];
__device__ __nv_bfloat16 g_yg_h [(size_t)MTOK * DI];
__device__ __nv_bfloat16 g_yg_l [(size_t)MTOK * DI];
__device__ __nv_bfloat16 g_Wo_h [(size_t)DM * DI];
__device__ __nv_bfloat16 g_Wo_l [(size_t)DM * DI];

// ---------------- float -> bf16 hi/lo split (supports strided source) ----------------
__global__ void split_bf16_kernel(const float* __restrict__ src, int ld, int cols,
                                  __nv_bfloat16* __restrict__ hi,
                                  __nv_bfloat16* __restrict__ lo, size_t n)
{
    size_t idx = (size_t)blockIdx.x * blockDim.x + threadIdx.x;
    if (idx >= n) return;
    size_t r = idx / cols, c = idx % cols;
    float x = src[r * ld + c];
    __nv_bfloat16 h = __float2bfloat16(x);
    float resid = x - __bfloat162float(h);
    hi[idx] = h;
    lo[idx] = __float2bfloat16(resid);
}

// ---------------- HMMA bf16x3 GEMM: C[M,N] = A[M,K] @ B[N,K]^T (+ epilogue) ----------------
// BM=128, BN=128, BK=64. 8 warps, each owns 64x32. SW128-swizzled smem + ldmatrix.
// hi/lo split: D = Ah*Bh + Ah*Bl + Al*Bh  (fp32 accum in registers)
// MODE 0: plain store; MODE 1: softplus(v + bias[n]); MODE 2: v + resid[m,n]
#define BM 128
#define BN 128
#define BK 64
#define TILEB 16384               // 128 rows * 128 bytes
#define GSMEM (4 * TILEB)         // Ah, Al, Bh, Bl

template<int MODE>
__global__ void __launch_bounds__(256, 2)
gemm_mma(const __nv_bfloat16* __restrict__ Ah, const __nv_bfloat16* __restrict__ Al,
         const __nv_bfloat16* __restrict__ Bh, const __nv_bfloat16* __restrict__ Bl,
         float* __restrict__ C, int ldc, int M, int N, int K,
         const float* __restrict__ bias,
         const float* __restrict__ resid, int ldr)
{
    extern __shared__ char sm[];
    char* sAh = sm;
    char* sAl = sm + TILEB;
    char* sBh = sm + 2 * TILEB;
    char* sBl = sm + 3 * TILEB;
    const uint32_t uAh = smem_to_u32(sAh);
    const uint32_t uAl = uAh + TILEB;
    const uint32_t uBh = uAh + 2 * TILEB;
    const uint32_t uBl = uAh + 3 * TILEB;

    const int tid  = threadIdx.x;
    const int lane = tid & 31;
    const int warp = tid >> 5;
    const int wm   = warp >> 2;     // 0..1  (64-row band)
    const int wn   = warp & 3;      // 0..3  (32-col band)
    const int m0   = blockIdx.y * BM;
    const int n0   = blockIdx.x * BN;

    float acc[4][4][4];
#pragma unroll
    for (int i = 0; i < 4; i++)
#pragma unroll
        for (int j = 0; j < 4; j++)
#pragma unroll
            for (int q = 0; q < 4; q++) acc[i][j][q] = 0.f;

    // ldmatrix per-lane smem offsets (fixed across chunks except k-unit)
    const int a_row = wm * 64 + (lane & 15);       // + mi*16
    const int a_ku  = lane >> 4;                   // 0 or 1 (16B k-unit within k16 step)
    const int b_row = wn * 32 + (lane & 7);        // + ni*8
    const int b_ku  = (lane >> 3) & 1;

    for (int k0 = 0; k0 < K; k0 += BK) {
        __syncthreads();   // protect previous iteration's smem reads
        // fill 4 tiles: 128 rows x 8 x 16B each
        for (int u = tid; u < 1024; u += 256) {
            const int r = u >> 3, c = u & 7;
            const uint32_t so = SMEM_SWIZZLE_128B((uint32_t)(r * 128 + c * 16));
            const size_t goA = (size_t)(m0 + r) * K + k0 + c * 8;
            *(uint4*)(sAh + so) = *(const uint4*)(Ah + goA);
            *(uint4*)(sAl + so) = *(const uint4*)(Al + goA);
            if (n0 + r < N) {
                const size_t goB = (size_t)(n0 + r) * K + k0 + c * 8;
                *(uint4*)(sBh + so) = *(const uint4*)(Bh + goB);
                *(uint4*)(sBl + so) = *(const uint4*)(Bl + goB);
            } else {
                const uint4 z = make_uint4(0, 0, 0, 0);
                *(uint4*)(sBh + so) = z;
                *(uint4*)(sBl + so) = z;
            }
        }
        __syncthreads();

#pragma unroll
        for (int kk = 0; kk < 4; kk++) {          // 4 x k16 per BK=64
            const int aun = kk * 2 + a_ku;
            const int bun = kk * 2 + b_ku;
            // load all B fragments for this k16 step (16 regs live)
            uint32_t bh[4][2], bl[4][2];
#pragma unroll
            for (int ni = 0; ni < 4; ni++) {
                const uint32_t off =
                    SMEM_SWIZZLE_128B((uint32_t)((b_row + ni * 8) * 128 + bun * 16));
                LDMATRIX_X2(bh[ni][0], bh[ni][1], uBh + off);
                LDMATRIX_X2(bl[ni][0], bl[ni][1], uBl + off);
            }
            // stream A fragments per 16-row band (8 regs live at a time)
#pragma unroll
            for (int mi = 0; mi < 4; mi++) {
                const uint32_t off =
                    SMEM_SWIZZLE_128B((uint32_t)((a_row + mi * 16) * 128 + aun * 16));
                uint32_t ah[4], al[4];
                LDMATRIX_X4(ah[0], ah[1], ah[2], ah[3], uAh + off);
                LDMATRIX_X4(al[0], al[1], al[2], al[3], uAl + off);
#pragma unroll
                for (int ni = 0; ni < 4; ni++) {
                    MMA16816(acc[mi][ni], ah, bh[ni]);
                    MMA16816(acc[mi][ni], ah, bl[ni]);
                    MMA16816(acc[mi][ni], al, bh[ni]);
                }
            }
        }
    }

    // epilogue: registers -> global (each thread owns 2x2 float2 per tile)
#pragma unroll
    for (int mi = 0; mi < 4; mi++) {
#pragma unroll
        for (int ni = 0; ni < 4; ni++) {
            const int m = m0 + wm * 64 + mi * 16 + (lane >> 2);
            const int n = n0 + wn * 32 + ni * 8 + (lane & 3) * 2;
            if (n < N) {
#pragma unroll
                for (int h = 0; h < 2; h++) {      // h=0: row m, h=1: row m+8
                    const int mm = m + h * 8;
                    float v0 = acc[mi][ni][h * 2 + 0];
                    float v1 = acc[mi][ni][h * 2 + 1];
                    if (MODE == 1) {
                        v0 += bias[n];     v1 += bias[n + 1];
                        v0 = (v0 > 20.f) ? v0 : log1pf(expf(v0));
                        v1 = (v1 > 20.f) ? v1 : log1pf(expf(v1));
                    }
                    if (MODE == 2) {
                        const float2 rr = *(const float2*)(resid + (size_t)mm * ldr + n);
                        v0 += rr.x; v1 += rr.y;
                    }
                    *(float2*)(C + (size_t)mm * ldc + n) = make_float2(v0, v1);
                }
            }
        }
    }
}

// ---------------- depthwise causal conv1d (k=4) + SiLU, fused hi/lo split ----------------
__global__ void conv_silu_kernel(const float* __restrict__ cw,
                                 const float* __restrict__ cb,
                                 __nv_bfloat16* __restrict__ uh,
                                 __nv_bfloat16* __restrict__ ul)
{
    const size_t idx = (size_t)blockIdx.x * blockDim.x + threadIdx.x;
    if (idx >= (size_t)MTOK * DI) return;
    const int d = (int)(idx % DI);
    const int m = (int)(idx / DI);
    const int t = m % LEN;

    const float w0 = cw[d * 4 + 0], w1 = cw[d * 4 + 1];
    const float w2 = cw[d * 4 + 2], w3 = cw[d * 4 + 3];
    float acc = cb[d];
    if (t >= 3) acc = fmaf(g_xz[(size_t)(m - 3) * (2 * DI) + d], w0, acc);
    if (t >= 2) acc = fmaf(g_xz[(size_t)(m - 2) * (2 * DI) + d], w1, acc);
    if (t >= 1) acc = fmaf(g_xz[(size_t)(m - 1) * (2 * DI) + d], w2, acc);
    acc = fmaf(g_xz[(size_t)m * (2 * DI) + d], w3, acc);
    const float sg = 1.f / (1.f + expf(-acc));
    const float uv = acc * sg;
    g_u[idx] = uv;
    __nv_bfloat16 h = __float2bfloat16(uv);
    uh[idx] = h;
    ul[idx] = __float2bfloat16(uv - __bfloat162float(h));
}

// ---------------- selective scan + skip + gate, fused hi/lo split ----------------
__global__ __launch_bounds__(256)
void scan_kernel(const float* __restrict__ A_log,
                 const float* __restrict__ Dp,
                 __nv_bfloat16* __restrict__ ygh,
                 __nv_bfloat16* __restrict__ ygl)
{
    const int tid  = threadIdx.x;
    const int wid  = tid >> 5;
    const int lane = tid & 31;
    const int half = lane >> 4;
    const int n    = lane & 15;

    const int blocks_per_batch = DI / 16;
    const int b      = blockIdx.x / blocks_per_batch;
    const int dchunk = blockIdx.x % blocks_per_batch;
    const int d      = dchunk * 16 + wid * 2 + half;

    const float a_coef = -expf(A_log[d * DS + n]);
    const float Dd     = Dp[d];
    float s = 0.f;

    const int mbase = b * LEN;
    for (int t = 0; t < LEN; t++) {
        const int m = mbase + t;
        const float dt = g_dlt[(size_t)m * DI + d];
        const float uu = g_u  [(size_t)m * DI + d];
        const float Bv = g_proj[(size_t)m * PROJW + DI + n];
        const float Cv = g_proj[(size_t)m * PROJW + DI + DS + n];

        const float dA = __expf(dt * a_coef);
        s = fmaf(s, dA, dt * Bv * uu);

        float p = s * Cv;
        p += __shfl_xor_sync(0xffffffffu, p, 8);
        p += __shfl_xor_sync(0xffffffffu, p, 4);
        p += __shfl_xor_sync(0xffffffffu, p, 2);
        p += __shfl_xor_sync(0xffffffffu, p, 1);

        if (n == 0) {
            const float zz = g_xz[(size_t)m * (2 * DI) + DI + d];
            const float y  = p + uu * Dd;
            const float sz = zz / (1.f + __expf(-zz));
            const float yv = y * sz;
            const size_t o = (size_t)m * DI + d;
            g_yg[o] = yv;
            __nv_bfloat16 h = __float2bfloat16(yv);
            ygh[o] = h;
            ygl[o] = __float2bfloat16(yv - __bfloat162float(h));
        }
    }
}

// ---------------- LayerNorm over last dim (1024), in-place on d_out ----------------
__global__ __launch_bounds__(256)
void layernorm_kernel(float* __restrict__ out,
                      const float* __restrict__ g,
                      const float* __restrict__ bta)
{
    const int m = blockIdx.x;
    const int tid = threadIdx.x;
    float* row = out + (size_t)m * DM;

    float4 v = ((const float4*)row)[tid];
    const float4 gg = ((const float4*)g)[tid];
    const float4 bb = ((const float4*)bta)[tid];

    __shared__ float sh[8];
    __shared__ float bc;

    float sv = v.x + v.y + v.z + v.w;
    for (int o = 16; o > 0; o >>= 1) sv += __shfl_xor_sync(0xffffffffu, sv, o);
    if ((tid & 31) == 0) sh[tid >> 5] = sv;
    __syncthreads();
    if (tid < 32) {
        float t2 = (tid < 8) ? sh[tid] : 0.f;
        for (int o = 4; o > 0; o >>= 1) t2 += __shfl_xor_sync(0xffffffffu, t2, o);
        if (tid == 0) bc = t2;
    }
    __syncthreads();
    const float mu = bc * (1.f / DM);
    __syncthreads();

    float dx0 = v.x - mu, dx1 = v.y - mu, dx2 = v.z - mu, dx3 = v.w - mu;
    float sq = dx0 * dx0 + dx1 * dx1 + dx2 * dx2 + dx3 * dx3;
    for (int o = 16; o > 0; o >>= 1) sq += __shfl_xor_sync(0xffffffffu, sq, o);
    if ((tid & 31) == 0) sh[tid >> 5] = sq;
    __syncthreads();
    if (tid < 32) {
        float t2 = (tid < 8) ? sh[tid] : 0.f;
        for (int o = 4; o > 0; o >>= 1) t2 += __shfl_xor_sync(0xffffffffu, t2, o);
        if (tid == 0) bc = t2;
    }
    __syncthreads();
    const float var = bc * (1.f / DM);
    const float inv = rsqrtf(var + 1e-5f);

    v.x = dx0 * inv * gg.x + bb.x;
    v.y = dx1 * inv * gg.y + bb.y;
    v.z = dx2 * inv * gg.z + bb.z;
    v.w = dx3 * inv * gg.w + bb.w;
    ((float4*)row)[tid] = v;
}

// ---------------- host launch ----------------
static inline unsigned cdiv_sz(size_t a, size_t b) { return (unsigned)((a + b - 1) / b); }

extern "C" void kernel_launch(void* const* d_in, const int* in_sizes, int n_in,
                              void* d_out, int out_size)
{
    const float* x      = (const float*)d_in[0];
    const float* W_in   = (const float*)d_in[1];
    const float* conv_w = (const float*)d_in[2];
    const float* conv_b = (const float*)d_in[3];
    const float* W_x    = (const float*)d_in[4];
    const float* W_dt   = (const float*)d_in[5];
    const float* b_dt   = (const float*)d_in[6];
    const float* A_log  = (const float*)d_in[7];
    const float* Dp     = (const float*)d_in[8];
    const float* W_out  = (const float*)d_in[9];
    const float* ln_g   = (const float*)d_in[10];
    const float* ln_b   = (const float*)d_in[11];
    float* out = (float*)d_out;

    float *xz, *u, *proj, *dlt, *yg;
    cudaGetSymbolAddress((void**)&xz,   g_xz);
    cudaGetSymbolAddress((void**)&u,    g_u);
    cudaGetSymbolAddress((void**)&proj, g_proj);
    cudaGetSymbolAddress((void**)&dlt,  g_dlt);
    cudaGetSymbolAddress((void**)&yg,   g_yg);

    __nv_bfloat16 *xh, *xl, *Wih, *Wil, *uh, *ul, *Wxh, *Wxl, *dih, *dil, *Wdh, *Wdl, *ygh, *ygl, *Woh, *Wol;
    cudaGetSymbolAddress((void**)&xh,  g_x_h);  cudaGetSymbolAddress((void**)&xl,  g_x_l);
    cudaGetSymbolAddress((void**)&Wih, g_Wi_h); cudaGetSymbolAddress((void**)&Wil, g_Wi_l);
    cudaGetSymbolAddress((void**)&uh,  g_u_h);  cudaGetSymbolAddress((void**)&ul,  g_u_l);
    cudaGetSymbolAddress((void**)&Wxh, g_Wx_h); cudaGetSymbolAddress((void**)&Wxl, g_Wx_l);
    cudaGetSymbolAddress((void**)&dih, g_di_h); cudaGetSymbolAddress((void**)&dil, g_di_l);
    cudaGetSymbolAddress((void**)&Wdh, g_Wd_h); cudaGetSymbolAddress((void**)&Wdl, g_Wd_l);
    cudaGetSymbolAddress((void**)&ygh, g_yg_h); cudaGetSymbolAddress((void**)&ygl, g_yg_l);
    cudaGetSymbolAddress((void**)&Woh, g_Wo_h); cudaGetSymbolAddress((void**)&Wol, g_Wo_l);

    cudaFuncSetAttribute(gemm_mma<0>, cudaFuncAttributeMaxDynamicSharedMemorySize, GSMEM);
    cudaFuncSetAttribute(gemm_mma<1>, cudaFuncAttributeMaxDynamicSharedMemorySize, GSMEM);
    cudaFuncSetAttribute(gemm_mma<2>, cudaFuncAttributeMaxDynamicSharedMemorySize, GSMEM);

    dim3 thr(256);

    // --- split conversions for static weights + x ---
    {
        size_t n;
        n = (size_t)MTOK * DM;
        split_bf16_kernel<<<cdiv_sz(n, 256), thr>>>(x, DM, DM, xh, xl, n);
        n = (size_t)2 * DI * DM;
        split_bf16_kernel<<<cdiv_sz(n, 256), thr>>>(W_in, DM, DM, Wih, Wil, n);
        n = (size_t)PROJW * DI;
        split_bf16_kernel<<<cdiv_sz(n, 256), thr>>>(W_x, DI, DI, Wxh, Wxl, n);
        n = (size_t)DI * DI;
        split_bf16_kernel<<<cdiv_sz(n, 256), thr>>>(W_dt, DI, DI, Wdh, Wdl, n);
        n = (size_t)DM * DI;
        split_bf16_kernel<<<cdiv_sz(n, 256), thr>>>(W_out, DI, DI, Woh, Wol, n);
    }

    // 1) xz = x @ W_in^T              (4096 x 4096, K=1024)
    gemm_mma<0><<<dim3((2 * DI) / BN, MTOK / BM), thr, GSMEM>>>(
        xh, xl, Wih, Wil, xz, 2 * DI, MTOK, 2 * DI, DM, nullptr, nullptr, 0);

    // 2) u = silu(causal_conv(xs) + cb)   [+ fused hi/lo split]
    conv_silu_kernel<<<cdiv_sz((size_t)MTOK * DI, 256), thr>>>(conv_w, conv_b, uh, ul);

    // 3) proj = u @ W_x^T             (4096 x 2080, K=2048)
    gemm_mma<0><<<dim3((PROJW + BN - 1) / BN, MTOK / BM), thr, GSMEM>>>(
        uh, ul, Wxh, Wxl, proj, PROJW, MTOK, PROJW, DI, nullptr, nullptr, 0);
    {
        // d_in part of proj (strided src, width 2048 of 2080)
        size_t n = (size_t)MTOK * DI;
        split_bf16_kernel<<<cdiv_sz(n, 256), thr>>>(proj, PROJW, DI, dih, dil, n);
    }

    // 4) delta = softplus(d_in @ W_dt^T + b_dt)
    gemm_mma<1><<<dim3(DI / BN, MTOK / BM), thr, GSMEM>>>(
        dih, dil, Wdh, Wdl, dlt, DI, MTOK, DI, DI, b_dt, nullptr, 0);

    // 5) selective scan + skip + gate -> yg   [+ fused hi/lo split]
    scan_kernel<<<BATCHN * (DI / 16), thr>>>(A_log, Dp, ygh, ygl);

    // 6) out = yg @ W_out^T + x       (4096 x 1024, K=2048)
    gemm_mma<2><<<dim3(DM / BN, MTOK / BM), thr, GSMEM>>>(
        ygh, ygl, Woh, Wol, out, DM, MTOK, DM, DI, nullptr, x, DM);

    // 7) layernorm in place
    layernorm_kernel<<<MTOK, thr>>>(out, ln_g, ln_b);
}

// round 9
// speedup vs baseline: 2.7048x; 1.8106x over previous
#include <cuda_runtime.h>
#include <cuda_bf16.h>
#include <math.h>
#include <cstdint>

// Problem constants
#define BATCHN 2
#define LEN    2048
#define DM     1024
#define DI     2048
#define DS     16
#define MTOK   (BATCHN*LEN)      // 4096 tokens
#define PROJW  (DI + 2*DS)       // 2080

__device__ __forceinline__ uint32_t smem_to_u32(const void* p) {
    uint32_t a;
    asm("{ .reg .u64 t; cvta.to.shared.u64 t, %1; cvt.u32.u64 %0, t; }" : "=r"(a) : "l"(p));
    return a;
}
#define SMEM_SWIZZLE_128B(byte_offset) \
    ((byte_offset) ^ (((byte_offset) >> 3) & 0x70))

#define LDMATRIX_X4(r0, r1, r2, r3, addr) \
    asm volatile("ldmatrix.sync.aligned.m8n8.x4.shared.b16 {%0,%1,%2,%3}, [%4];" \
        : "=r"(r0), "=r"(r1), "=r"(r2), "=r"(r3) : "r"(addr))
#define LDMATRIX_X2(r0, r1, addr) \
    asm volatile("ldmatrix.sync.aligned.m8n8.x2.shared.b16 {%0,%1}, [%2];" \
        : "=r"(r0), "=r"(r1) : "r"(addr))
#define MMA16816(d, a, b) \
    asm volatile("mma.sync.aligned.m16n8k16.row.col.f32.bf16.bf16.f32 " \
        "{%0,%1,%2,%3}, {%4,%5,%6,%7}, {%8,%9}, {%0,%1,%2,%3};" \
        : "+f"((d)[0]), "+f"((d)[1]), "+f"((d)[2]), "+f"((d)[3]) \
        : "r"((a)[0]), "r"((a)[1]), "r"((a)[2]), "r"((a)[3]), \
          "r"((b)[0]), "r"((b)[1]))

#define CP_ASYNC16(dst, src) \
    asm volatile("cp.async.cg.shared.global [%0], [%1], 16;" :: "r"(dst), "l"(src))
#define CP_ASYNC16_ZF(dst, src, sz) \
    asm volatile("cp.async.cg.shared.global [%0], [%1], 16, %2;" :: "r"(dst), "l"(src), "r"(sz))
#define CP_COMMIT() asm volatile("cp.async.commit_group;" ::: "memory")
#define CP_WAIT1()  asm volatile("cp.async.wait_group 1;" ::: "memory")
#define CP_WAIT0()  asm volatile("cp.async.wait_group 0;" ::: "memory")

// ---------------- scratch (device globals; no allocation allowed) ----------------
__device__ float g_xz  [(size_t)MTOK * 2*DI];   // in_proj output [xs | z]
__device__ float g_u   [(size_t)MTOK * DI];     // conv+silu output
__device__ float g_proj[(size_t)MTOK * PROJW];  // x_proj output [d_in | B | C]
__device__ float g_dlt [(size_t)MTOK * DI];     // softplus(dt)
__device__ float g_yg  [(size_t)MTOK * DI];     // scan output * silu(z)

// bf16 hi/lo split operand buffers
__device__ __nv_bfloat16 g_x_h  [(size_t)MTOK * DM];
__device__ __nv_bfloat16 g_x_l  [(size_t)MTOK * DM];
__device__ __nv_bfloat16 g_Wi_h [(size_t)2*DI * DM];
__device__ __nv_bfloat16 g_Wi_l [(size_t)2*DI * DM];
__device__ __nv_bfloat16 g_u_h  [(size_t)MTOK * DI];
__device__ __nv_bfloat16 g_u_l  [(size_t)MTOK * DI];
__device__ __nv_bfloat16 g_Wx_h [(size_t)PROJW * DI];
__device__ __nv_bfloat16 g_Wx_l [(size_t)PROJW * DI];
__device__ __nv_bfloat16 g_di_h [(size_t)MTOK * DI];
__device__ __nv_bfloat16 g_di_l [(size_t)MTOK * DI];
__device__ __nv_bfloat16 g_Wd_h [(size_t)DI * DI];
__device__ __nv_bfloat16 g_Wd_l [(size_t)DI * DI];
__device__ __nv_bfloat16 g_yg_h [(size_t)MTOK * DI];
__device__ __nv_bfloat16 g_yg_l [(size_t)MTOK * DI];
__device__ __nv_bfloat16 g_Wo_h [(size_t)DM * DI];
__device__ __nv_bfloat16 g_Wo_l [(size_t)DM * DI];

// ---------------- float -> bf16 hi/lo split (supports strided source) ----------------
__global__ void split_bf16_kernel(const float* __restrict__ src, int ld, int cols,
                                  __nv_bfloat16* __restrict__ hi,
                                  __nv_bfloat16* __restrict__ lo, size_t n)
{
    size_t idx = (size_t)blockIdx.x * blockDim.x + threadIdx.x;
    if (idx >= n) return;
    size_t r = idx / cols, c = idx % cols;
    float x = src[r * ld + c];
    __nv_bfloat16 h = __float2bfloat16(x);
    float resid = x - __bfloat162float(h);
    hi[idx] = h;
    lo[idx] = __float2bfloat16(resid);
}

// ---------------- HMMA bf16x3 GEMM with cp.async 2-stage pipeline ----------------
// BM=128, BN=128, BK=64. 8 warps each own 64x32. SW128 smem + ldmatrix.
// hi/lo split: D = Ah*Bh + Ah*Bl + Al*Bh  (fp32 accum in registers)
// MODE 0: plain store; MODE 1: softplus(v+bias[n]); MODE 2: v+resid; MODE 3: store + hi/lo split of cols < DI
#define BM 128
#define BN 128
#define BK 64
#define TILEB 16384               // 128 rows * 128 bytes
#define STAGEB (4 * TILEB)        // Ah, Al, Bh, Bl
#define GSMEM (2 * STAGEB)        // 2 stages = 128 KB

template<int MODE>
__global__ void __launch_bounds__(256, 1)
gemm_mma(const __nv_bfloat16* __restrict__ Ah, const __nv_bfloat16* __restrict__ Al,
         const __nv_bfloat16* __restrict__ Bh, const __nv_bfloat16* __restrict__ Bl,
         float* __restrict__ C, int ldc, int M, int N, int K,
         const float* __restrict__ bias,
         const float* __restrict__ resid, int ldr,
         __nv_bfloat16* __restrict__ oh, __nv_bfloat16* __restrict__ ol)
{
    extern __shared__ char smbuf[];
    const uint32_t usm = smem_to_u32(smbuf);

    const int tid  = threadIdx.x;
    const int lane = tid & 31;
    const int warp = tid >> 5;
    const int wm   = warp >> 2;     // 0..1  (64-row band)
    const int wn   = warp & 3;      // 0..3  (32-col band)
    const int m0   = blockIdx.y * BM;
    const int n0   = blockIdx.x * BN;

    float acc[4][4][4];
#pragma unroll
    for (int i = 0; i < 4; i++)
#pragma unroll
        for (int j = 0; j < 4; j++)
#pragma unroll
            for (int q = 0; q < 4; q++) acc[i][j][q] = 0.f;

    // per-thread load coords: 1024 16B units per tile, 4 units/thread
    const int lr = tid >> 1;                 // 0..127 (row)
    const int lc2 = (tid & 1) * 4;           // 0 or 4 (first of 4 units)
    const bool bvalid = (n0 + lr) < N;
    const uint32_t bsz = bvalid ? 16u : 0u;
    const size_t aoff = (size_t)(m0 + lr) * K;
    const size_t boff = (size_t)(bvalid ? (n0 + lr) : 0) * K;

    // ldmatrix per-lane offsets
    const int a_row = wm * 64 + (lane & 15);
    const int a_ku  = lane >> 4;
    const int b_row = wn * 32 + (lane & 7);
    const int b_ku  = (lane >> 3) & 1;

    const int nch = K / BK;

    // ---- stage loader: 4 cp.async x4 per thread ----
    auto load_stage = [&](int ci, int s) {
        const uint32_t st = usm + s * STAGEB;
        const int k0 = ci * BK;
#pragma unroll
        for (int q = 0; q < 4; q++) {
            const int c = lc2 + q;
            const uint32_t so = SMEM_SWIZZLE_128B((uint32_t)(lr * 128 + c * 16));
            const size_t ke = (size_t)(k0 + c * 8);
            CP_ASYNC16(st + so,              Ah + aoff + ke);
            CP_ASYNC16(st + TILEB + so,      Al + aoff + ke);
            CP_ASYNC16_ZF(st + 2*TILEB + so, Bh + boff + ke, bsz);
            CP_ASYNC16_ZF(st + 3*TILEB + so, Bl + boff + ke, bsz);
        }
        CP_COMMIT();
    };

    load_stage(0, 0);

    for (int i = 0; i < nch; i++) {
        if (i + 1 < nch) { load_stage(i + 1, (i + 1) & 1); CP_WAIT1(); }
        else             { CP_WAIT0(); }
        __syncthreads();

        const uint32_t st = usm + (i & 1) * STAGEB;
        const uint32_t uAh = st, uAl = st + TILEB, uBh = st + 2*TILEB, uBl = st + 3*TILEB;

#pragma unroll
        for (int kk = 0; kk < 4; kk++) {
            const int aun = kk * 2 + a_ku;
            const int bun = kk * 2 + b_ku;
            uint32_t bh[4][2], bl[4][2];
#pragma unroll
            for (int ni = 0; ni < 4; ni++) {
                const uint32_t off =
                    SMEM_SWIZZLE_128B((uint32_t)((b_row + ni * 8) * 128 + bun * 16));
                LDMATRIX_X2(bh[ni][0], bh[ni][1], uBh + off);
                LDMATRIX_X2(bl[ni][0], bl[ni][1], uBl + off);
            }
#pragma unroll
            for (int mi = 0; mi < 4; mi++) {
                const uint32_t off =
                    SMEM_SWIZZLE_128B((uint32_t)((a_row + mi * 16) * 128 + aun * 16));
                uint32_t ah[4], al[4];
                LDMATRIX_X4(ah[0], ah[1], ah[2], ah[3], uAh + off);
                LDMATRIX_X4(al[0], al[1], al[2], al[3], uAl + off);
#pragma unroll
                for (int ni = 0; ni < 4; ni++) {
                    MMA16816(acc[mi][ni], ah, bh[ni]);
                    MMA16816(acc[mi][ni], ah, bl[ni]);
                    MMA16816(acc[mi][ni], al, bh[ni]);
                }
            }
        }
        __syncthreads();
    }

    // epilogue
#pragma unroll
    for (int mi = 0; mi < 4; mi++) {
#pragma unroll
        for (int ni = 0; ni < 4; ni++) {
            const int m = m0 + wm * 64 + mi * 16 + (lane >> 2);
            const int n = n0 + wn * 32 + ni * 8 + (lane & 3) * 2;
            if (n < N) {
#pragma unroll
                for (int h = 0; h < 2; h++) {
                    const int mm = m + h * 8;
                    float v0 = acc[mi][ni][h * 2 + 0];
                    float v1 = acc[mi][ni][h * 2 + 1];
                    if (MODE == 1) {
                        v0 += bias[n];     v1 += bias[n + 1];
                        v0 = (v0 > 20.f) ? v0 : log1pf(expf(v0));
                        v1 = (v1 > 20.f) ? v1 : log1pf(expf(v1));
                    }
                    if (MODE == 2) {
                        const float2 rr = *(const float2*)(resid + (size_t)mm * ldr + n);
                        v0 += rr.x; v1 += rr.y;
                    }
                    *(float2*)(C + (size_t)mm * ldc + n) = make_float2(v0, v1);
                    if (MODE == 3 && n < DI) {
                        const __nv_bfloat16 h0 = __float2bfloat16(v0);
                        const __nv_bfloat16 h1 = __float2bfloat16(v1);
                        const size_t o = (size_t)mm * DI + n;
                        oh[o]     = h0;
                        oh[o + 1] = h1;
                        ol[o]     = __float2bfloat16(v0 - __bfloat162float(h0));
                        ol[o + 1] = __float2bfloat16(v1 - __bfloat162float(h1));
                    }
                }
            }
        }
    }
}

// ---------------- depthwise causal conv1d (k=4) + SiLU, fused hi/lo split ----------------
__global__ void conv_silu_kernel(const float* __restrict__ cw,
                                 const float* __restrict__ cb,
                                 __nv_bfloat16* __restrict__ uh,
                                 __nv_bfloat16* __restrict__ ul)
{
    const size_t idx = (size_t)blockIdx.x * blockDim.x + threadIdx.x;
    if (idx >= (size_t)MTOK * DI) return;
    const int d = (int)(idx % DI);
    const int m = (int)(idx / DI);
    const int t = m % LEN;

    const float w0 = cw[d * 4 + 0], w1 = cw[d * 4 + 1];
    const float w2 = cw[d * 4 + 2], w3 = cw[d * 4 + 3];
    float acc = cb[d];
    if (t >= 3) acc = fmaf(g_xz[(size_t)(m - 3) * (2 * DI) + d], w0, acc);
    if (t >= 2) acc = fmaf(g_xz[(size_t)(m - 2) * (2 * DI) + d], w1, acc);
    if (t >= 1) acc = fmaf(g_xz[(size_t)(m - 1) * (2 * DI) + d], w2, acc);
    acc = fmaf(g_xz[(size_t)m * (2 * DI) + d], w3, acc);
    const float sg = 1.f / (1.f + expf(-acc));
    const float uv = acc * sg;
    g_u[idx] = uv;
    __nv_bfloat16 h = __float2bfloat16(uv);
    uh[idx] = h;
    ul[idx] = __float2bfloat16(uv - __bfloat162float(h));
}

// ---------------- selective scan + skip + gate, windowed prefetch ----------------
#define SW 8
__global__ __launch_bounds__(256)
void scan_kernel(const float* __restrict__ A_log,
                 const float* __restrict__ Dp,
                 __nv_bfloat16* __restrict__ ygh,
                 __nv_bfloat16* __restrict__ ygl)
{
    const int tid  = threadIdx.x;
    const int wid  = tid >> 5;
    const int lane = tid & 31;
    const int half = lane >> 4;
    const int n    = lane & 15;

    const int blocks_per_batch = DI / 16;
    const int b      = blockIdx.x / blocks_per_batch;
    const int dchunk = blockIdx.x % blocks_per_batch;
    const int d      = dchunk * 16 + wid * 2 + half;

    const float a_coef = -expf(A_log[d * DS + n]);
    const float Dd     = Dp[d];
    float s = 0.f;

    const int mbase = b * LEN;
    for (int t0 = 0; t0 < LEN; t0 += SW) {
        float dt8[SW], uu8[SW], Bv8[SW], Cv8[SW], zz8[SW];
#pragma unroll
        for (int j = 0; j < SW; j++) {
            const int m = mbase + t0 + j;
            dt8[j] = g_dlt[(size_t)m * DI + d];
            uu8[j] = g_u  [(size_t)m * DI + d];
            Bv8[j] = g_proj[(size_t)m * PROJW + DI + n];
            Cv8[j] = g_proj[(size_t)m * PROJW + DI + DS + n];
            zz8[j] = g_xz[(size_t)m * (2 * DI) + DI + d];
        }
#pragma unroll
        for (int j = 0; j < SW; j++) {
            const float dA = __expf(dt8[j] * a_coef);
            s = fmaf(s, dA, dt8[j] * Bv8[j] * uu8[j]);

            float p = s * Cv8[j];
            p += __shfl_xor_sync(0xffffffffu, p, 8);
            p += __shfl_xor_sync(0xffffffffu, p, 4);
            p += __shfl_xor_sync(0xffffffffu, p, 2);
            p += __shfl_xor_sync(0xffffffffu, p, 1);

            if (n == 0) {
                const float y  = p + uu8[j] * Dd;
                const float sz = zz8[j] / (1.f + __expf(-zz8[j]));
                const float yv = y * sz;
                const size_t o = (size_t)(mbase + t0 + j) * DI + d;
                g_yg[o] = yv;
                __nv_bfloat16 h = __float2bfloat16(yv);
                ygh[o] = h;
                ygl[o] = __float2bfloat16(yv - __bfloat162float(h));
            }
        }
    }
}

// ---------------- LayerNorm over last dim (1024), in-place on d_out ----------------
__global__ __launch_bounds__(256)
void layernorm_kernel(float* __restrict__ out,
                      const float* __restrict__ g,
                      const float* __restrict__ bta)
{
    const int m = blockIdx.x;
    const int tid = threadIdx.x;
    float* row = out + (size_t)m * DM;

    float4 v = ((const float4*)row)[tid];
    const float4 gg = ((const float4*)g)[tid];
    const float4 bb = ((const float4*)bta)[tid];

    __shared__ float sh[8];
    __shared__ float bc;

    float sv = v.x + v.y + v.z + v.w;
    for (int o = 16; o > 0; o >>= 1) sv += __shfl_xor_sync(0xffffffffu, sv, o);
    if ((tid & 31) == 0) sh[tid >> 5] = sv;
    __syncthreads();
    if (tid < 32) {
        float t2 = (tid < 8) ? sh[tid] : 0.f;
        for (int o = 4; o > 0; o >>= 1) t2 += __shfl_xor_sync(0xffffffffu, t2, o);
        if (tid == 0) bc = t2;
    }
    __syncthreads();
    const float mu = bc * (1.f / DM);
    __syncthreads();

    float dx0 = v.x - mu, dx1 = v.y - mu, dx2 = v.z - mu, dx3 = v.w - mu;
    float sq = dx0 * dx0 + dx1 * dx1 + dx2 * dx2 + dx3 * dx3;
    for (int o = 16; o > 0; o >>= 1) sq += __shfl_xor_sync(0xffffffffu, sq, o);
    if ((tid & 31) == 0) sh[tid >> 5] = sq;
    __syncthreads();
    if (tid < 32) {
        float t2 = (tid < 8) ? sh[tid] : 0.f;
        for (int o = 4; o > 0; o >>= 1) t2 += __shfl_xor_sync(0xffffffffu, t2, o);
        if (tid == 0) bc = t2;
    }
    __syncthreads();
    const float var = bc * (1.f / DM);
    const float inv = rsqrtf(var + 1e-5f);

    v.x = dx0 * inv * gg.x + bb.x;
    v.y = dx1 * inv * gg.y + bb.y;
    v.z = dx2 * inv * gg.z + bb.z;
    v.w = dx3 * inv * gg.w + bb.w;
    ((float4*)row)[tid] = v;
}

// ---------------- host launch ----------------
static inline unsigned cdiv_sz(size_t a, size_t b) { return (unsigned)((a + b - 1) / b); }

extern "C" void kernel_launch(void* const* d_in, const int* in_sizes, int n_in,
                              void* d_out, int out_size)
{
    const float* x      = (const float*)d_in[0];
    const float* W_in   = (const float*)d_in[1];
    const float* conv_w = (const float*)d_in[2];
    const float* conv_b = (const float*)d_in[3];
    const float* W_x    = (const float*)d_in[4];
    const float* W_dt   = (const float*)d_in[5];
    const float* b_dt   = (const float*)d_in[6];
    const float* A_log  = (const float*)d_in[7];
    const float* Dp     = (const float*)d_in[8];
    const float* W_out  = (const float*)d_in[9];
    const float* ln_g   = (const float*)d_in[10];
    const float* ln_b   = (const float*)d_in[11];
    float* out = (float*)d_out;

    float *xz, *u, *proj, *dlt, *yg;
    cudaGetSymbolAddress((void**)&xz,   g_xz);
    cudaGetSymbolAddress((void**)&u,    g_u);
    cudaGetSymbolAddress((void**)&proj, g_proj);
    cudaGetSymbolAddress((void**)&dlt,  g_dlt);
    cudaGetSymbolAddress((void**)&yg,   g_yg);

    __nv_bfloat16 *xh, *xl, *Wih, *Wil, *uh, *ul, *Wxh, *Wxl, *dih, *dil, *Wdh, *Wdl, *ygh, *ygl, *Woh, *Wol;
    cudaGetSymbolAddress((void**)&xh,  g_x_h);  cudaGetSymbolAddress((void**)&xl,  g_x_l);
    cudaGetSymbolAddress((void**)&Wih, g_Wi_h); cudaGetSymbolAddress((void**)&Wil, g_Wi_l);
    cudaGetSymbolAddress((void**)&uh,  g_u_h);  cudaGetSymbolAddress((void**)&ul,  g_u_l);
    cudaGetSymbolAddress((void**)&Wxh, g_Wx_h); cudaGetSymbolAddress((void**)&Wxl, g_Wx_l);
    cudaGetSymbolAddress((void**)&dih, g_di_h); cudaGetSymbolAddress((void**)&dil, g_di_l);
    cudaGetSymbolAddress((void**)&Wdh, g_Wd_h); cudaGetSymbolAddress((void**)&Wdl, g_Wd_l);
    cudaGetSymbolAddress((void**)&ygh, g_yg_h); cudaGetSymbolAddress((void**)&ygl, g_yg_l);
    cudaGetSymbolAddress((void**)&Woh, g_Wo_h); cudaGetSymbolAddress((void**)&Wol, g_Wo_l);

    cudaFuncSetAttribute(gemm_mma<0>, cudaFuncAttributeMaxDynamicSharedMemorySize, GSMEM);
    cudaFuncSetAttribute(gemm_mma<1>, cudaFuncAttributeMaxDynamicSharedMemorySize, GSMEM);
    cudaFuncSetAttribute(gemm_mma<2>, cudaFuncAttributeMaxDynamicSharedMemorySize, GSMEM);
    cudaFuncSetAttribute(gemm_mma<3>, cudaFuncAttributeMaxDynamicSharedMemorySize, GSMEM);

    dim3 thr(256);

    // --- split conversions for static weights + x ---
    {
        size_t n;
        n = (size_t)MTOK * DM;
        split_bf16_kernel<<<cdiv_sz(n, 256), thr>>>(x, DM, DM, xh, xl, n);
        n = (size_t)2 * DI * DM;
        split_bf16_kernel<<<cdiv_sz(n, 256), thr>>>(W_in, DM, DM, Wih, Wil, n);
        n = (size_t)PROJW * DI;
        split_bf16_kernel<<<cdiv_sz(n, 256), thr>>>(W_x, DI, DI, Wxh, Wxl, n);
        n = (size_t)DI * DI;
        split_bf16_kernel<<<cdiv_sz(n, 256), thr>>>(W_dt, DI, DI, Wdh, Wdl, n);
        n = (size_t)DM * DI;
        split_bf16_kernel<<<cdiv_sz(n, 256), thr>>>(W_out, DI, DI, Woh, Wol, n);
    }

    // 1) xz = x @ W_in^T              (4096 x 4096, K=1024)
    gemm_mma<0><<<dim3((2 * DI) / BN, MTOK / BM), thr, GSMEM>>>(
        xh, xl, Wih, Wil, xz, 2 * DI, MTOK, 2 * DI, DM, nullptr, nullptr, 0, nullptr, nullptr);

    // 2) u = silu(causal_conv(xs) + cb)   [+ fused hi/lo split]
    conv_silu_kernel<<<cdiv_sz((size_t)MTOK * DI, 256), thr>>>(conv_w, conv_b, uh, ul);

    // 3) proj = u @ W_x^T             (4096 x 2080, K=2048)  [+ fused d_in split]
    gemm_mma<3><<<dim3((PROJW + BN - 1) / BN, MTOK / BM), thr, GSMEM>>>(
        uh, ul, Wxh, Wxl, proj, PROJW, MTOK, PROJW, DI, nullptr, nullptr, 0, dih, dil);

    // 4) delta = softplus(d_in @ W_dt^T + b_dt)
    gemm_mma<1><<<dim3(DI / BN, MTOK / BM), thr, GSMEM>>>(
        dih, dil, Wdh, Wdl, dlt, DI, MTOK, DI, DI, b_dt, nullptr, 0, nullptr, nullptr);

    // 5) selective scan + skip + gate -> yg   [+ fused hi/lo split]
    scan_kernel<<<BATCHN * (DI / 16), thr>>>(A_log, Dp, ygh, ygl);

    // 6) out = yg @ W_out^T + x       (4096 x 1024, K=2048)
    gemm_mma<2><<<dim3(DM / BN, MTOK / BM), thr, GSMEM>>>(
        ygh, ygl, Woh, Wol, out, DM, MTOK, DM, DI, nullptr, x, DM, nullptr, nullptr);

    // 7) layernorm in place
    layernorm_kernel<<<MTOK, thr>>>(out, ln_g, ln_b);
}

// round 10
// speedup vs baseline: 2.7088x; 1.0015x over previous
#include <cuda_runtime.h>
#include <cuda_bf16.h>
#include <math.h>
#include <cstdint>

// Problem constants
#define BATCHN 2
#define LEN    2048
#define DM     1024
#define DI     2048
#define DS     16
#define MTOK   (BATCHN*LEN)      // 4096 tokens
#define PROJW  (DI + 2*DS)       // 2080

__device__ __forceinline__ uint32_t smem_to_u32(const void* p) {
    uint32_t a;
    asm("{ .reg .u64 t; cvta.to.shared.u64 t, %1; cvt.u32.u64 %0, t; }" : "=r"(a) : "l"(p));
    return a;
}
#define SMEM_SWIZZLE_128B(byte_offset) \
    ((byte_offset) ^ (((byte_offset) >> 3) & 0x70))

#define LDMATRIX_X4(r0, r1, r2, r3, addr) \
    asm volatile("ldmatrix.sync.aligned.m8n8.x4.shared.b16 {%0,%1,%2,%3}, [%4];" \
        : "=r"(r0), "=r"(r1), "=r"(r2), "=r"(r3) : "r"(addr))
#define LDMATRIX_X2(r0, r1, addr) \
    asm volatile("ldmatrix.sync.aligned.m8n8.x2.shared.b16 {%0,%1}, [%2];" \
        : "=r"(r0), "=r"(r1) : "r"(addr))
#define MMA16816(d, a, b) \
    asm volatile("mma.sync.aligned.m16n8k16.row.col.f32.bf16.bf16.f32 " \
        "{%0,%1,%2,%3}, {%4,%5,%6,%7}, {%8,%9}, {%0,%1,%2,%3};" \
        : "+f"((d)[0]), "+f"((d)[1]), "+f"((d)[2]), "+f"((d)[3]) \
        : "r"((a)[0]), "r"((a)[1]), "r"((a)[2]), "r"((a)[3]), \
          "r"((b)[0]), "r"((b)[1]))

#define CP_ASYNC16(dst, src) \
    asm volatile("cp.async.cg.shared.global [%0], [%1], 16;" :: "r"(dst), "l"(src))
#define CP_ASYNC16_ZF(dst, src, sz) \
    asm volatile("cp.async.cg.shared.global [%0], [%1], 16, %2;" :: "r"(dst), "l"(src), "r"(sz))
#define CP_COMMIT() asm volatile("cp.async.commit_group;" ::: "memory")
#define CP_WAIT2()  asm volatile("cp.async.wait_group 2;" ::: "memory")
#define CP_WAIT1()  asm volatile("cp.async.wait_group 1;" ::: "memory")
#define CP_WAIT0()  asm volatile("cp.async.wait_group 0;" ::: "memory")

// ---------------- scratch (device globals; no allocation allowed) ----------------
__device__ float g_xz  [(size_t)MTOK * 2*DI];   // in_proj output [xs | z]
__device__ float g_u   [(size_t)MTOK * DI];     // conv+silu output
__device__ float g_proj[(size_t)MTOK * PROJW];  // x_proj output [d_in | B | C]
__device__ float g_dlt [(size_t)MTOK * DI];     // softplus(dt)
__device__ float g_yg  [(size_t)MTOK * DI];     // scan output * silu(z)

// bf16 hi/lo split operand buffers
__device__ __nv_bfloat16 g_x_h  [(size_t)MTOK * DM];
__device__ __nv_bfloat16 g_x_l  [(size_t)MTOK * DM];
__device__ __nv_bfloat16 g_Wi_h [(size_t)2*DI * DM];
__device__ __nv_bfloat16 g_Wi_l [(size_t)2*DI * DM];
__device__ __nv_bfloat16 g_u_h  [(size_t)MTOK * DI];
__device__ __nv_bfloat16 g_u_l  [(size_t)MTOK * DI];
__device__ __nv_bfloat16 g_Wx_h [(size_t)PROJW * DI];
__device__ __nv_bfloat16 g_Wx_l [(size_t)PROJW * DI];
__device__ __nv_bfloat16 g_di_h [(size_t)MTOK * DI];
__device__ __nv_bfloat16 g_di_l [(size_t)MTOK * DI];
__device__ __nv_bfloat16 g_Wd_h [(size_t)DI * DI];
__device__ __nv_bfloat16 g_Wd_l [(size_t)DI * DI];
__device__ __nv_bfloat16 g_yg_h [(size_t)MTOK * DI];
__device__ __nv_bfloat16 g_yg_l [(size_t)MTOK * DI];
__device__ __nv_bfloat16 g_Wo_h [(size_t)DM * DI];
__device__ __nv_bfloat16 g_Wo_l [(size_t)DM * DI];

// ---------------- float -> bf16 hi/lo split (supports strided source) ----------------
__global__ void split_bf16_kernel(const float* __restrict__ src, int ld, int cols,
                                  __nv_bfloat16* __restrict__ hi,
                                  __nv_bfloat16* __restrict__ lo, size_t n)
{
    size_t idx = (size_t)blockIdx.x * blockDim.x + threadIdx.x;
    if (idx >= n) return;
    size_t r = idx / cols, c = idx % cols;
    float x = src[r * ld + c];
    __nv_bfloat16 h = __float2bfloat16(x);
    float resid = x - __bfloat162float(h);
    hi[idx] = h;
    lo[idx] = __float2bfloat16(resid);
}

// ---------------- HMMA bf16x3 GEMM with cp.async 3-stage pipeline ----------------
// BM=128, BN=128, BK=64. 8 warps each own 64x32. SW128 smem + ldmatrix.
// hi/lo split: D = Ah*Bh + Ah*Bl + Al*Bh  (fp32 accum in registers)
// MODE 0: plain store; MODE 1: softplus(v+bias[n]); MODE 2: v+resid; MODE 3: store + hi/lo split of cols < DI
#define BM 128
#define BN 128
#define BK 64
#define TILEB 16384               // 128 rows * 128 bytes
#define STAGEB (4 * TILEB)        // Ah, Al, Bh, Bl = 64 KB
#define NSTAGE 3
#define GSMEM (NSTAGE * STAGEB)   // 192 KB

template<int MODE>
__global__ void __launch_bounds__(256, 1)
gemm_mma(const __nv_bfloat16* __restrict__ Ah, const __nv_bfloat16* __restrict__ Al,
         const __nv_bfloat16* __restrict__ Bh, const __nv_bfloat16* __restrict__ Bl,
         float* __restrict__ C, int ldc, int M, int N, int K,
         const float* __restrict__ bias,
         const float* __restrict__ resid, int ldr,
         __nv_bfloat16* __restrict__ oh, __nv_bfloat16* __restrict__ ol)
{
    extern __shared__ char smbuf[];
    const uint32_t usm = smem_to_u32(smbuf);

    const int tid  = threadIdx.x;
    const int lane = tid & 31;
    const int warp = tid >> 5;
    const int wm   = warp >> 2;     // 0..1  (64-row band)
    const int wn   = warp & 3;      // 0..3  (32-col band)
    const int m0   = blockIdx.y * BM;
    const int n0   = blockIdx.x * BN;

    float acc[4][4][4];
#pragma unroll
    for (int i = 0; i < 4; i++)
#pragma unroll
        for (int j = 0; j < 4; j++)
#pragma unroll
            for (int q = 0; q < 4; q++) acc[i][j][q] = 0.f;

    // per-thread load coords: 1024 16B units per tile, 4 units/thread
    const int lr = tid >> 1;                 // 0..127 (row)
    const int lc2 = (tid & 1) * 4;           // 0 or 4 (first of 4 units)
    const bool bvalid = (n0 + lr) < N;
    const uint32_t bsz = bvalid ? 16u : 0u;
    const size_t aoff = (size_t)(m0 + lr) * K;
    const size_t boff = (size_t)(bvalid ? (n0 + lr) : 0) * K;

    // ldmatrix per-lane offsets
    const int a_row = wm * 64 + (lane & 15);
    const int a_ku  = lane >> 4;
    const int b_row = wn * 32 + (lane & 7);
    const int b_ku  = (lane >> 3) & 1;

    const int nch = K / BK;

    // ---- stage loader: 4 cp.async x4 per thread ----
    auto load_stage = [&](int ci, int s) {
        const uint32_t st = usm + s * STAGEB;
        const int k0 = ci * BK;
#pragma unroll
        for (int q = 0; q < 4; q++) {
            const int c = lc2 + q;
            const uint32_t so = SMEM_SWIZZLE_128B((uint32_t)(lr * 128 + c * 16));
            const size_t ke = (size_t)(k0 + c * 8);
            CP_ASYNC16(st + so,              Ah + aoff + ke);
            CP_ASYNC16(st + TILEB + so,      Al + aoff + ke);
            CP_ASYNC16_ZF(st + 2*TILEB + so, Bh + boff + ke, bsz);
            CP_ASYNC16_ZF(st + 3*TILEB + so, Bl + boff + ke, bsz);
        }
        CP_COMMIT();
    };

    // prologue: fill stages 0 and 1
    load_stage(0, 0);
    load_stage(1, 1);

    for (int i = 0; i < nch; i++) {
        // issue load for i+2 into stage (i+2)%3 — that stage was consumed in
        // iteration i-1 and is protected by iteration i-1's trailing barrier.
        if (i + 2 < nch) { load_stage(i + 2, (i + 2) % NSTAGE); CP_WAIT2(); }
        else if (i + 2 == nch) { CP_WAIT1(); }
        else                   { CP_WAIT0(); }
        __syncthreads();

        const uint32_t st = usm + (i % NSTAGE) * STAGEB;
        const uint32_t uAh = st, uAl = st + TILEB, uBh = st + 2*TILEB, uBl = st + 3*TILEB;

#pragma unroll
        for (int kk = 0; kk < 4; kk++) {
            const int aun = kk * 2 + a_ku;
            const int bun = kk * 2 + b_ku;
            uint32_t bh[4][2], bl[4][2];
#pragma unroll
            for (int ni = 0; ni < 4; ni++) {
                const uint32_t off =
                    SMEM_SWIZZLE_128B((uint32_t)((b_row + ni * 8) * 128 + bun * 16));
                LDMATRIX_X2(bh[ni][0], bh[ni][1], uBh + off);
                LDMATRIX_X2(bl[ni][0], bl[ni][1], uBl + off);
            }
#pragma unroll
            for (int mi = 0; mi < 4; mi++) {
                const uint32_t off =
                    SMEM_SWIZZLE_128B((uint32_t)((a_row + mi * 16) * 128 + aun * 16));
                uint32_t ah[4], al[4];
                LDMATRIX_X4(ah[0], ah[1], ah[2], ah[3], uAh + off);
                LDMATRIX_X4(al[0], al[1], al[2], al[3], uAl + off);
#pragma unroll
                for (int ni = 0; ni < 4; ni++) {
                    MMA16816(acc[mi][ni], ah, bh[ni]);
                    MMA16816(acc[mi][ni], ah, bl[ni]);
                    MMA16816(acc[mi][ni], al, bh[ni]);
                }
            }
        }
        __syncthreads();
    }

    // epilogue
#pragma unroll
    for (int mi = 0; mi < 4; mi++) {
#pragma unroll
        for (int ni = 0; ni < 4; ni++) {
            const int m = m0 + wm * 64 + mi * 16 + (lane >> 2);
            const int n = n0 + wn * 32 + ni * 8 + (lane & 3) * 2;
            if (n < N) {
#pragma unroll
                for (int h = 0; h < 2; h++) {
                    const int mm = m + h * 8;
                    float v0 = acc[mi][ni][h * 2 + 0];
                    float v1 = acc[mi][ni][h * 2 + 1];
                    if (MODE == 1) {
                        v0 += bias[n];     v1 += bias[n + 1];
                        v0 = (v0 > 20.f) ? v0 : log1pf(expf(v0));
                        v1 = (v1 > 20.f) ? v1 : log1pf(expf(v1));
                    }
                    if (MODE == 2) {
                        const float2 rr = *(const float2*)(resid + (size_t)mm * ldr + n);
                        v0 += rr.x; v1 += rr.y;
                    }
                    *(float2*)(C + (size_t)mm * ldc + n) = make_float2(v0, v1);
                    if (MODE == 3 && n < DI) {
                        const __nv_bfloat16 h0 = __float2bfloat16(v0);
                        const __nv_bfloat16 h1 = __float2bfloat16(v1);
                        const size_t o = (size_t)mm * DI + n;
                        oh[o]     = h0;
                        oh[o + 1] = h1;
                        ol[o]     = __float2bfloat16(v0 - __bfloat162float(h0));
                        ol[o + 1] = __float2bfloat16(v1 - __bfloat162float(h1));
                    }
                }
            }
        }
    }
}

// ---------------- depthwise causal conv1d (k=4) + SiLU, fused hi/lo split ----------------
__global__ void conv_silu_kernel(const float* __restrict__ cw,
                                 const float* __restrict__ cb,
                                 __nv_bfloat16* __restrict__ uh,
                                 __nv_bfloat16* __restrict__ ul)
{
    const size_t idx = (size_t)blockIdx.x * blockDim.x + threadIdx.x;
    if (idx >= (size_t)MTOK * DI) return;
    const int d = (int)(idx % DI);
    const int m = (int)(idx / DI);
    const int t = m % LEN;

    const float w0 = cw[d * 4 + 0], w1 = cw[d * 4 + 1];
    const float w2 = cw[d * 4 + 2], w3 = cw[d * 4 + 3];
    float acc = cb[d];
    if (t >= 3) acc = fmaf(g_xz[(size_t)(m - 3) * (2 * DI) + d], w0, acc);
    if (t >= 2) acc = fmaf(g_xz[(size_t)(m - 2) * (2 * DI) + d], w1, acc);
    if (t >= 1) acc = fmaf(g_xz[(size_t)(m - 1) * (2 * DI) + d], w2, acc);
    acc = fmaf(g_xz[(size_t)m * (2 * DI) + d], w3, acc);
    const float sg = 1.f / (1.f + expf(-acc));
    const float uv = acc * sg;
    g_u[idx] = uv;
    __nv_bfloat16 h = __float2bfloat16(uv);
    uh[idx] = h;
    ul[idx] = __float2bfloat16(uv - __bfloat162float(h));
}

// ---------------- selective scan + skip + gate, windowed prefetch ----------------
#define SW 8
__global__ __launch_bounds__(256)
void scan_kernel(const float* __restrict__ A_log,
                 const float* __restrict__ Dp,
                 __nv_bfloat16* __restrict__ ygh,
                 __nv_bfloat16* __restrict__ ygl)
{
    const int tid  = threadIdx.x;
    const int wid  = tid >> 5;
    const int lane = tid & 31;
    const int half = lane >> 4;
    const int n    = lane & 15;

    const int blocks_per_batch = DI / 16;
    const int b      = blockIdx.x / blocks_per_batch;
    const int dchunk = blockIdx.x % blocks_per_batch;
    const int d      = dchunk * 16 + wid * 2 + half;

    const float a_coef = -expf(A_log[d * DS + n]);
    const float Dd     = Dp[d];
    float s = 0.f;

    const int mbase = b * LEN;
    for (int t0 = 0; t0 < LEN; t0 += SW) {
        float dt8[SW], uu8[SW], Bv8[SW], Cv8[SW], zz8[SW];
#pragma unroll
        for (int j = 0; j < SW; j++) {
            const int m = mbase + t0 + j;
            dt8[j] = g_dlt[(size_t)m * DI + d];
            uu8[j] = g_u  [(size_t)m * DI + d];
            Bv8[j] = g_proj[(size_t)m * PROJW + DI + n];
            Cv8[j] = g_proj[(size_t)m * PROJW + DI + DS + n];
            zz8[j] = g_xz[(size_t)m * (2 * DI) + DI + d];
        }
#pragma unroll
        for (int j = 0; j < SW; j++) {
            const float dA = __expf(dt8[j] * a_coef);
            s = fmaf(s, dA, dt8[j] * Bv8[j] * uu8[j]);

            float p = s * Cv8[j];
            p += __shfl_xor_sync(0xffffffffu, p, 8);
            p += __shfl_xor_sync(0xffffffffu, p, 4);
            p += __shfl_xor_sync(0xffffffffu, p, 2);
            p += __shfl_xor_sync(0xffffffffu, p, 1);

            if (n == 0) {
                const float y  = p + uu8[j] * Dd;
                const float sz = zz8[j] / (1.f + __expf(-zz8[j]));
                const float yv = y * sz;
                const size_t o = (size_t)(mbase + t0 + j) * DI + d;
                g_yg[o] = yv;
                __nv_bfloat16 h = __float2bfloat16(yv);
                ygh[o] = h;
                ygl[o] = __float2bfloat16(yv - __bfloat162float(h));
            }
        }
    }
}

// ---------------- LayerNorm over last dim (1024), in-place on d_out ----------------
__global__ __launch_bounds__(256)
void layernorm_kernel(float* __restrict__ out,
                      const float* __restrict__ g,
                      const float* __restrict__ bta)
{
    const int m = blockIdx.x;
    const int tid = threadIdx.x;
    float* row = out + (size_t)m * DM;

    float4 v = ((const float4*)row)[tid];
    const float4 gg = ((const float4*)g)[tid];
    const float4 bb = ((const float4*)bta)[tid];

    __shared__ float sh[8];
    __shared__ float bc;

    float sv = v.x + v.y + v.z + v.w;
    for (int o = 16; o > 0; o >>= 1) sv += __shfl_xor_sync(0xffffffffu, sv, o);
    if ((tid & 31) == 0) sh[tid >> 5] = sv;
    __syncthreads();
    if (tid < 32) {
        float t2 = (tid < 8) ? sh[tid] : 0.f;
        for (int o = 4; o > 0; o >>= 1) t2 += __shfl_xor_sync(0xffffffffu, t2, o);
        if (tid == 0) bc = t2;
    }
    __syncthreads();
    const float mu = bc * (1.f / DM);
    __syncthreads();

    float dx0 = v.x - mu, dx1 = v.y - mu, dx2 = v.z - mu, dx3 = v.w - mu;
    float sq = dx0 * dx0 + dx1 * dx1 + dx2 * dx2 + dx3 * dx3;
    for (int o = 16; o > 0; o >>= 1) sq += __shfl_xor_sync(0xffffffffu, sq, o);
    if ((tid & 31) == 0) sh[tid >> 5] = sq;
    __syncthreads();
    if (tid < 32) {
        float t2 = (tid < 8) ? sh[tid] : 0.f;
        for (int o = 4; o > 0; o >>= 1) t2 += __shfl_xor_sync(0xffffffffu, t2, o);
        if (tid == 0) bc = t2;
    }
    __syncthreads();
    const float var = bc * (1.f / DM);
    const float inv = rsqrtf(var + 1e-5f);

    v.x = dx0 * inv * gg.x + bb.x;
    v.y = dx1 * inv * gg.y + bb.y;
    v.z = dx2 * inv * gg.z + bb.z;
    v.w = dx3 * inv * gg.w + bb.w;
    ((float4*)row)[tid] = v;
}

// ---------------- host launch ----------------
static inline unsigned cdiv_sz(size_t a, size_t b) { return (unsigned)((a + b - 1) / b); }

extern "C" void kernel_launch(void* const* d_in, const int* in_sizes, int n_in,
                              void* d_out, int out_size)
{
    const float* x      = (const float*)d_in[0];
    const float* W_in   = (const float*)d_in[1];
    const float* conv_w = (const float*)d_in[2];
    const float* conv_b = (const float*)d_in[3];
    const float* W_x    = (const float*)d_in[4];
    const float* W_dt   = (const float*)d_in[5];
    const float* b_dt   = (const float*)d_in[6];
    const float* A_log  = (const float*)d_in[7];
    const float* Dp     = (const float*)d_in[8];
    const float* W_out  = (const float*)d_in[9];
    const float* ln_g   = (const float*)d_in[10];
    const float* ln_b   = (const float*)d_in[11];
    float* out = (float*)d_out;

    float *xz, *u, *proj, *dlt, *yg;
    cudaGetSymbolAddress((void**)&xz,   g_xz);
    cudaGetSymbolAddress((void**)&u,    g_u);
    cudaGetSymbolAddress((void**)&proj, g_proj);
    cudaGetSymbolAddress((void**)&dlt,  g_dlt);
    cudaGetSymbolAddress((void**)&yg,   g_yg);

    __nv_bfloat16 *xh, *xl, *Wih, *Wil, *uh, *ul, *Wxh, *Wxl, *dih, *dil, *Wdh, *Wdl, *ygh, *ygl, *Woh, *Wol;
    cudaGetSymbolAddress((void**)&xh,  g_x_h);  cudaGetSymbolAddress((void**)&xl,  g_x_l);
    cudaGetSymbolAddress((void**)&Wih, g_Wi_h); cudaGetSymbolAddress((void**)&Wil, g_Wi_l);
    cudaGetSymbolAddress((void**)&uh,  g_u_h);  cudaGetSymbolAddress((void**)&ul,  g_u_l);
    cudaGetSymbolAddress((void**)&Wxh, g_Wx_h); cudaGetSymbolAddress((void**)&Wxl, g_Wx_l);
    cudaGetSymbolAddress((void**)&dih, g_di_h); cudaGetSymbolAddress((void**)&dil, g_di_l);
    cudaGetSymbolAddress((void**)&Wdh, g_Wd_h); cudaGetSymbolAddress((void**)&Wdl, g_Wd_l);
    cudaGetSymbolAddress((void**)&ygh, g_yg_h); cudaGetSymbolAddress((void**)&ygl, g_yg_l);
    cudaGetSymbolAddress((void**)&Woh, g_Wo_h); cudaGetSymbolAddress((void**)&Wol, g_Wo_l);

    cudaFuncSetAttribute(gemm_mma<0>, cudaFuncAttributeMaxDynamicSharedMemorySize, GSMEM);
    cudaFuncSetAttribute(gemm_mma<1>, cudaFuncAttributeMaxDynamicSharedMemorySize, GSMEM);
    cudaFuncSetAttribute(gemm_mma<2>, cudaFuncAttributeMaxDynamicSharedMemorySize, GSMEM);
    cudaFuncSetAttribute(gemm_mma<3>, cudaFuncAttributeMaxDynamicSharedMemorySize, GSMEM);

    dim3 thr(256);

    // --- split conversions for static weights + x ---
    {
        size_t n;
        n = (size_t)MTOK * DM;
        split_bf16_kernel<<<cdiv_sz(n, 256), thr>>>(x, DM, DM, xh, xl, n);
        n = (size_t)2 * DI * DM;
        split_bf16_kernel<<<cdiv_sz(n, 256), thr>>>(W_in, DM, DM, Wih, Wil, n);
        n = (size_t)PROJW * DI;
        split_bf16_kernel<<<cdiv_sz(n, 256), thr>>>(W_x, DI, DI, Wxh, Wxl, n);
        n = (size_t)DI * DI;
        split_bf16_kernel<<<cdiv_sz(n, 256), thr>>>(W_dt, DI, DI, Wdh, Wdl, n);
        n = (size_t)DM * DI;
        split_bf16_kernel<<<cdiv_sz(n, 256), thr>>>(W_out, DI, DI, Woh, Wol, n);
    }

    // 1) xz = x @ W_in^T              (4096 x 4096, K=1024)
    gemm_mma<0><<<dim3((2 * DI) / BN, MTOK / BM), thr, GSMEM>>>(
        xh, xl, Wih, Wil, xz, 2 * DI, MTOK, 2 * DI, DM, nullptr, nullptr, 0, nullptr, nullptr);

    // 2) u = silu(causal_conv(xs) + cb)   [+ fused hi/lo split]
    conv_silu_kernel<<<cdiv_sz((size_t)MTOK * DI, 256), thr>>>(conv_w, conv_b, uh, ul);

    // 3) proj = u @ W_x^T             (4096 x 2080, K=2048)  [+ fused d_in split]
    gemm_mma<3><<<dim3((PROJW + BN - 1) / BN, MTOK / BM), thr, GSMEM>>>(
        uh, ul, Wxh, Wxl, proj, PROJW, MTOK, PROJW, DI, nullptr, nullptr, 0, dih, dil);

    // 4) delta = softplus(d_in @ W_dt^T + b_dt)
    gemm_mma<1><<<dim3(DI / BN, MTOK / BM), thr, GSMEM>>>(
        dih, dil, Wdh, Wdl, dlt, DI, MTOK, DI, DI, b_dt, nullptr, 0, nullptr, nullptr);

    // 5) selective scan + skip + gate -> yg   [+ fused hi/lo split]
    scan_kernel<<<BATCHN * (DI / 16), thr>>>(A_log, Dp, ygh, ygl);

    // 6) out = yg @ W_out^T + x       (4096 x 1024, K=2048)
    gemm_mma<2><<<dim3(DM / BN, MTOK / BM), thr, GSMEM>>>(
        ygh, ygl, Woh, Wol, out, DM, MTOK, DM, DI, nullptr, x, DM, nullptr, nullptr);

    // 7) layernorm in place
    layernorm_kernel<<<MTOK, thr>>>(out, ln_g, ln_b);
}

// round 13
// speedup vs baseline: 2.9110x; 1.0746x over previous
#include <cuda_runtime.h>
#include <cuda_bf16.h>
#include <math.h>
#include <cstdint>

// Problem constants
#define BATCHN 2
#define LEN    2048
#define DM     1024
#define DI     2048
#define DS     16
#define MTOK   (BATCHN*LEN)      // 4096 tokens
#define PROJW  (DI + 2*DS)       // 2080

__device__ __forceinline__ uint32_t smem_to_u32(const void* p) {
    uint32_t a;
    asm("{ .reg .u64 t; cvta.to.shared.u64 t, %1; cvt.u32.u64 %0, t; }" : "=r"(a) : "l"(p));
    return a;
}
#define SMEM_SWIZZLE_128B(byte_offset) \
    ((byte_offset) ^ (((byte_offset) >> 3) & 0x70))

#define LDMATRIX_X4(r0, r1, r2, r3, addr) \
    asm volatile("ldmatrix.sync.aligned.m8n8.x4.shared.b16 {%0,%1,%2,%3}, [%4];" \
        : "=r"(r0), "=r"(r1), "=r"(r2), "=r"(r3) : "r"(addr))
#define LDMATRIX_X2(r0, r1, addr) \
    asm volatile("ldmatrix.sync.aligned.m8n8.x2.shared.b16 {%0,%1}, [%2];" \
        : "=r"(r0), "=r"(r1) : "r"(addr))
#define MMA16816(d, a, b) \
    asm volatile("mma.sync.aligned.m16n8k16.row.col.f32.bf16.bf16.f32 " \
        "{%0,%1,%2,%3}, {%4,%5,%6,%7}, {%8,%9}, {%0,%1,%2,%3};" \
        : "+f"((d)[0]), "+f"((d)[1]), "+f"((d)[2]), "+f"((d)[3]) \
        : "r"((a)[0]), "r"((a)[1]), "r"((a)[2]), "r"((a)[3]), \
          "r"((b)[0]), "r"((b)[1]))

#define CP_ASYNC16(dst, src) \
    asm volatile("cp.async.cg.shared.global [%0], [%1], 16;" :: "r"(dst), "l"(src))
#define CP_ASYNC16_ZF(dst, src, sz) \
    asm volatile("cp.async.cg.shared.global [%0], [%1], 16, %2;" :: "r"(dst), "l"(src), "r"(sz))
#define CP_COMMIT() asm volatile("cp.async.commit_group;" ::: "memory")
#define CP_WAIT1()  asm volatile("cp.async.wait_group 1;" ::: "memory")
#define CP_WAIT0()  asm volatile("cp.async.wait_group 0;" ::: "memory")

// ---------------- scratch (device globals; no allocation allowed) ----------------
__device__ float g_xz  [(size_t)MTOK * 2*DI];   // in_proj output [xs | z]
__device__ float g_u   [(size_t)MTOK * DI];     // conv+silu output
__device__ float g_proj[(size_t)MTOK * PROJW];  // x_proj output [d_in | B | C]
__device__ float g_dlt [(size_t)MTOK * DI];     // softplus(dt)
__device__ float g_yg  [(size_t)MTOK * DI];     // scan output * silu(z)

// bf16 hi/lo split operand buffers
__device__ __nv_bfloat16 g_x_h  [(size_t)MTOK * DM];
__device__ __nv_bfloat16 g_x_l  [(size_t)MTOK * DM];
__device__ __nv_bfloat16 g_Wi_h [(size_t)2*DI * DM];
__device__ __nv_bfloat16 g_Wi_l [(size_t)2*DI * DM];
__device__ __nv_bfloat16 g_u_h  [(size_t)MTOK * DI];
__device__ __nv_bfloat16 g_u_l  [(size_t)MTOK * DI];
__device__ __nv_bfloat16 g_Wx_h [(size_t)PROJW * DI];
__device__ __nv_bfloat16 g_Wx_l [(size_t)PROJW * DI];
__device__ __nv_bfloat16 g_di_h [(size_t)MTOK * DI];
__device__ __nv_bfloat16 g_di_l [(size_t)MTOK * DI];
__device__ __nv_bfloat16 g_Wd_h [(size_t)DI * DI];
__device__ __nv_bfloat16 g_Wd_l [(size_t)DI * DI];
__device__ __nv_bfloat16 g_yg_h [(size_t)MTOK * DI];
__device__ __nv_bfloat16 g_yg_l [(size_t)MTOK * DI];
__device__ __nv_bfloat16 g_Wo_h [(size_t)DM * DI];
__device__ __nv_bfloat16 g_Wo_l [(size_t)DM * DI];

// ---------------- float -> bf16 hi/lo split (supports strided source) ----------------
__global__ void split_bf16_kernel(const float* __restrict__ src, int ld, int cols,
                                  __nv_bfloat16* __restrict__ hi,
                                  __nv_bfloat16* __restrict__ lo, size_t n)
{
    size_t idx = (size_t)blockIdx.x * blockDim.x + threadIdx.x;
    if (idx >= n) return;
    size_t r = idx / cols, c = idx % cols;
    float x = src[r * ld + c];
    __nv_bfloat16 h = __float2bfloat16(x);
    float resid = x - __bfloat162float(h);
    hi[idx] = h;
    lo[idx] = __float2bfloat16(resid);
}

// ---------------- HMMA bf16x3 GEMM, 512 threads, cp.async 2-stage pipeline ----------------
// BM=256, BN=128, BK=64. 16 warps each own 64x32 (wm 0..3, wn 0..3). SW128 smem + ldmatrix.
// hi/lo split: D = Ah*Bh + Ah*Bl + Al*Bh  (fp32 accum in registers)
// MODE 0: plain store; MODE 1: softplus(v+bias[n]); MODE 2: v+resid; MODE 3: store + hi/lo split of cols < DI
#define BM 256
#define BN 128
#define BK 64
#define ATILEB 32768              // 256 rows * 128 bytes
#define BTILEB 16384              // 128 rows * 128 bytes
#define STAGEB (2*ATILEB + 2*BTILEB)  // Ah, Al, Bh, Bl = 96 KB
#define NSTAGE 2
#define GSMEM (NSTAGE * STAGEB)   // 192 KB

template<int MODE>
__global__ void __launch_bounds__(512, 1)
gemm_mma(const __nv_bfloat16* __restrict__ Ah, const __nv_bfloat16* __restrict__ Al,
         const __nv_bfloat16* __restrict__ Bh, const __nv_bfloat16* __restrict__ Bl,
         float* __restrict__ C, int ldc, int M, int N, int K,
         const float* __restrict__ bias,
         const float* __restrict__ resid, int ldr,
         __nv_bfloat16* __restrict__ oh, __nv_bfloat16* __restrict__ ol)
{
    extern __shared__ char smbuf[];
    const uint32_t usm = smem_to_u32(smbuf);

    const int tid  = threadIdx.x;
    const int lane = tid & 31;
    const int warp = tid >> 5;      // 0..15
    const int wm   = warp >> 2;     // 0..3  (64-row band)
    const int wn   = warp & 3;      // 0..3  (32-col band)
    const int m0   = blockIdx.y * BM;
    const int n0   = blockIdx.x * BN;

    float acc[4][4][4];
#pragma unroll
    for (int i = 0; i < 4; i++)
#pragma unroll
        for (int j = 0; j < 4; j++)
#pragma unroll
            for (int q = 0; q < 4; q++) acc[i][j][q] = 0.f;

    // per-thread load coords
    // A: 2048 16B-units per tile; 512 thr * 4 units (x2 for hi/lo)
    const int lrA = tid >> 1;                // 0..255 (row)
    const int lcA = (tid & 1) * 4;           // 0 or 4
    // B: 1024 16B-units per tile; 512 thr * 2 units (x2 for hi/lo)
    const int lrB = tid >> 2;                // 0..127 (row)
    const int lcB = (tid & 3) * 2;           // 0,2,4,6
    const bool bvalid = (n0 + lrB) < N;
    const uint32_t bsz = bvalid ? 16u : 0u;
    const size_t aoff = (size_t)(m0 + lrA) * K;
    const size_t boff = (size_t)(bvalid ? (n0 + lrB) : 0) * K;

    // ldmatrix per-lane offsets
    const int a_row = wm * 64 + (lane & 15);
    const int a_ku  = lane >> 4;
    const int b_row = wn * 32 + (lane & 7);
    const int b_ku  = (lane >> 3) & 1;

    const int nch = K / BK;

    // ---- stage loader ----
    auto load_stage = [&](int ci, int s) {
        const uint32_t st = usm + s * STAGEB;
        const int k0 = ci * BK;
#pragma unroll
        for (int q = 0; q < 4; q++) {
            const int c = lcA + q;
            const uint32_t so = SMEM_SWIZZLE_128B((uint32_t)(lrA * 128 + c * 16));
            const size_t ke = (size_t)(k0 + c * 8);
            CP_ASYNC16(st + so,          Ah + aoff + ke);
            CP_ASYNC16(st + ATILEB + so, Al + aoff + ke);
        }
#pragma unroll
        for (int q = 0; q < 2; q++) {
            const int c = lcB + q;
            const uint32_t so = SMEM_SWIZZLE_128B((uint32_t)(lrB * 128 + c * 16));
            const size_t ke = (size_t)(k0 + c * 8);
            CP_ASYNC16_ZF(st + 2*ATILEB + so,          Bh + boff + ke, bsz);
            CP_ASYNC16_ZF(st + 2*ATILEB + BTILEB + so, Bl + boff + ke, bsz);
        }
        CP_COMMIT();
    };

    load_stage(0, 0);

    for (int i = 0; i < nch; i++) {
        if (i + 1 < nch) { load_stage(i + 1, (i + 1) & 1); CP_WAIT1(); }
        else             { CP_WAIT0(); }
        __syncthreads();

        const uint32_t st  = usm + (i & 1) * STAGEB;
        const uint32_t uAh = st;
        const uint32_t uAl = st + ATILEB;
        const uint32_t uBh = st + 2*ATILEB;
        const uint32_t uBl = st + 2*ATILEB + BTILEB;

#pragma unroll
        for (int kk = 0; kk < 4; kk++) {
            const int aun = kk * 2 + a_ku;
            const int bun = kk * 2 + b_ku;
            uint32_t bh[4][2], bl[4][2];
#pragma unroll
            for (int ni = 0; ni < 4; ni++) {
                const uint32_t off =
                    SMEM_SWIZZLE_128B((uint32_t)((b_row + ni * 8) * 128 + bun * 16));
                LDMATRIX_X2(bh[ni][0], bh[ni][1], uBh + off);
                LDMATRIX_X2(bl[ni][0], bl[ni][1], uBl + off);
            }
#pragma unroll
            for (int mi = 0; mi < 4; mi++) {
                const uint32_t off =
                    SMEM_SWIZZLE_128B((uint32_t)((a_row + mi * 16) * 128 + aun * 16));
                uint32_t ah[4], al[4];
                LDMATRIX_X4(ah[0], ah[1], ah[2], ah[3], uAh + off);
                LDMATRIX_X4(al[0], al[1], al[2], al[3], uAl + off);
#pragma unroll
                for (int ni = 0; ni < 4; ni++) {
                    MMA16816(acc[mi][ni], ah, bh[ni]);
                    MMA16816(acc[mi][ni], ah, bl[ni]);
                    MMA16816(acc[mi][ni], al, bh[ni]);
                }
            }
        }
        __syncthreads();
    }

    // epilogue
#pragma unroll
    for (int mi = 0; mi < 4; mi++) {
#pragma unroll
        for (int ni = 0; ni < 4; ni++) {
            const int m = m0 + wm * 64 + mi * 16 + (lane >> 2);
            const int n = n0 + wn * 32 + ni * 8 + (lane & 3) * 2;
            if (n < N) {
#pragma unroll
                for (int h = 0; h < 2; h++) {
                    const int mm = m + h * 8;
                    float v0 = acc[mi][ni][h * 2 + 0];
                    float v1 = acc[mi][ni][h * 2 + 1];
                    if (MODE == 1) {
                        v0 += bias[n];     v1 += bias[n + 1];
                        v0 = (v0 > 20.f) ? v0 : log1pf(expf(v0));
                        v1 = (v1 > 20.f) ? v1 : log1pf(expf(v1));
                    }
                    if (MODE == 2) {
                        const float2 rr = *(const float2*)(resid + (size_t)mm * ldr + n);
                        v0 += rr.x; v1 += rr.y;
                    }
                    *(float2*)(C + (size_t)mm * ldc + n) = make_float2(v0, v1);
                    if (MODE == 3 && n < DI) {
                        const __nv_bfloat16 h0 = __float2bfloat16(v0);
                        const __nv_bfloat16 h1 = __float2bfloat16(v1);
                        const size_t o = (size_t)mm * DI + n;
                        oh[o]     = h0;
                        oh[o + 1] = h1;
                        ol[o]     = __float2bfloat16(v0 - __bfloat162float(h0));
                        ol[o + 1] = __float2bfloat16(v1 - __bfloat162float(h1));
                    }
                }
            }
        }
    }
}

// ---------------- depthwise causal conv1d (k=4) + SiLU, fused hi/lo split ----------------
__global__ void conv_silu_kernel(const float* __restrict__ cw,
                                 const float* __restrict__ cb,
                                 __nv_bfloat16* __restrict__ uh,
                                 __nv_bfloat16* __restrict__ ul)
{
    const size_t idx = (size_t)blockIdx.x * blockDim.x + threadIdx.x;
    if (idx >= (size_t)MTOK * DI) return;
    const int d = (int)(idx % DI);
    const int m = (int)(idx / DI);
    const int t = m % LEN;

    const float w0 = cw[d * 4 + 0], w1 = cw[d * 4 + 1];
    const float w2 = cw[d * 4 + 2], w3 = cw[d * 4 + 3];
    float acc = cb[d];
    if (t >= 3) acc = fmaf(g_xz[(size_t)(m - 3) * (2 * DI) + d], w0, acc);
    if (t >= 2) acc = fmaf(g_xz[(size_t)(m - 2) * (2 * DI) + d], w1, acc);
    if (t >= 1) acc = fmaf(g_xz[(size_t)(m - 1) * (2 * DI) + d], w2, acc);
    acc = fmaf(g_xz[(size_t)m * (2 * DI) + d], w3, acc);
    const float sg = 1.f / (1.f + expf(-acc));
    const float uv = acc * sg;
    g_u[idx] = uv;
    __nv_bfloat16 h = __float2bfloat16(uv);
    uh[idx] = h;
    ul[idx] = __float2bfloat16(uv - __bfloat162float(h));
}

// ---------------- selective scan + skip + gate, windowed prefetch ----------------
#define SW 8
__global__ __launch_bounds__(256)
void scan_kernel(const float* __restrict__ A_log,
                 const float* __restrict__ Dp,
                 __nv_bfloat16* __restrict__ ygh,
                 __nv_bfloat16* __restrict__ ygl)
{
    const int tid  = threadIdx.x;
    const int wid  = tid >> 5;
    const int lane = tid & 31;
    const int half = lane >> 4;
    const int n    = lane & 15;

    const int blocks_per_batch = DI / 16;
    const int b      = blockIdx.x / blocks_per_batch;
    const int dchunk = blockIdx.x % blocks_per_batch;
    const int d      = dchunk * 16 + wid * 2 + half;

    const float a_coef = -expf(A_log[d * DS + n]);
    const float Dd     = Dp[d];
    float s = 0.f;

    const int mbase = b * LEN;
    for (int t0 = 0; t0 < LEN; t0 += SW) {
        float dt8[SW], uu8[SW], Bv8[SW], Cv8[SW], zz8[SW];
#pragma unroll
        for (int j = 0; j < SW; j++) {
            const int m = mbase + t0 + j;
            dt8[j] = g_dlt[(size_t)m * DI + d];
            uu8[j] = g_u  [(size_t)m * DI + d];
            Bv8[j] = g_proj[(size_t)m * PROJW + DI + n];
            Cv8[j] = g_proj[(size_t)m * PROJW + DI + DS + n];
            zz8[j] = g_xz[(size_t)m * (2 * DI) + DI + d];
        }
#pragma unroll
        for (int j = 0; j < SW; j++) {
            const float dA = __expf(dt8[j] * a_coef);
            s = fmaf(s, dA, dt8[j] * Bv8[j] * uu8[j]);

            float p = s * Cv8[j];
            p += __shfl_xor_sync(0xffffffffu, p, 8);
            p += __shfl_xor_sync(0xffffffffu, p, 4);
            p += __shfl_xor_sync(0xffffffffu, p, 2);
            p += __shfl_xor_sync(0xffffffffu, p, 1);

            if (n == 0) {
                const float y  = p + uu8[j] * Dd;
                const float sz = zz8[j] / (1.f + __expf(-zz8[j]));
                const float yv = y * sz;
                const size_t o = (size_t)(mbase + t0 + j) * DI + d;
                g_yg[o] = yv;
                __nv_bfloat16 h = __float2bfloat16(yv);
                ygh[o] = h;
                ygl[o] = __float2bfloat16(yv - __bfloat162float(h));
            }
        }
    }
}

// ---------------- LayerNorm over last dim (1024), in-place on d_out ----------------
__global__ __launch_bounds__(256)
void layernorm_kernel(float* __restrict__ out,
                      const float* __restrict__ g,
                      const float* __restrict__ bta)
{
    const int m = blockIdx.x;
    const int tid = threadIdx.x;
    float* row = out + (size_t)m * DM;

    float4 v = ((const float4*)row)[tid];
    const float4 gg = ((const float4*)g)[tid];
    const float4 bb = ((const float4*)bta)[tid];

    __shared__ float sh[8];
    __shared__ float bc;

    float sv = v.x + v.y + v.z + v.w;
    for (int o = 16; o > 0; o >>= 1) sv += __shfl_xor_sync(0xffffffffu, sv, o);
    if ((tid & 31) == 0) sh[tid >> 5] = sv;
    __syncthreads();
    if (tid < 32) {
        float t2 = (tid < 8) ? sh[tid] : 0.f;
        for (int o = 4; o > 0; o >>= 1) t2 += __shfl_xor_sync(0xffffffffu, t2, o);
        if (tid == 0) bc = t2;
    }
    __syncthreads();
    const float mu = bc * (1.f / DM);
    __syncthreads();

    float dx0 = v.x - mu, dx1 = v.y - mu, dx2 = v.z - mu, dx3 = v.w - mu;
    float sq = dx0 * dx0 + dx1 * dx1 + dx2 * dx2 + dx3 * dx3;
    for (int o = 16; o > 0; o >>= 1) sq += __shfl_xor_sync(0xffffffffu, sq, o);
    if ((tid & 31) == 0) sh[tid >> 5] = sq;
    __syncthreads();
    if (tid < 32) {
        float t2 = (tid < 8) ? sh[tid] : 0.f;
        for (int o = 4; o > 0; o >>= 1) t2 += __shfl_xor_sync(0xffffffffu, t2, o);
        if (tid == 0) bc = t2;
    }
    __syncthreads();
    const float var = bc * (1.f / DM);
    const float inv = rsqrtf(var + 1e-5f);

    v.x = dx0 * inv * gg.x + bb.x;
    v.y = dx1 * inv * gg.y + bb.y;
    v.z = dx2 * inv * gg.z + bb.z;
    v.w = dx3 * inv * gg.w + bb.w;
    ((float4*)row)[tid] = v;
}

// ---------------- host launch ----------------
static inline unsigned cdiv_sz(size_t a, size_t b) { return (unsigned)((a + b - 1) / b); }

extern "C" void kernel_launch(void* const* d_in, const int* in_sizes, int n_in,
                              void* d_out, int out_size)
{
    const float* x      = (const float*)d_in[0];
    const float* W_in   = (const float*)d_in[1];
    const float* conv_w = (const float*)d_in[2];
    const float* conv_b = (const float*)d_in[3];
    const float* W_x    = (const float*)d_in[4];
    const float* W_dt   = (const float*)d_in[5];
    const float* b_dt   = (const float*)d_in[6];
    const float* A_log  = (const float*)d_in[7];
    const float* Dp     = (const float*)d_in[8];
    const float* W_out  = (const float*)d_in[9];
    const float* ln_g   = (const float*)d_in[10];
    const float* ln_b   = (const float*)d_in[11];
    float* out = (float*)d_out;

    float *xz, *u, *proj, *dlt, *yg;
    cudaGetSymbolAddress((void**)&xz,   g_xz);
    cudaGetSymbolAddress((void**)&u,    g_u);
    cudaGetSymbolAddress((void**)&proj, g_proj);
    cudaGetSymbolAddress((void**)&dlt,  g_dlt);
    cudaGetSymbolAddress((void**)&yg,   g_yg);

    __nv_bfloat16 *xh, *xl, *Wih, *Wil, *uh, *ul, *Wxh, *Wxl, *dih, *dil, *Wdh, *Wdl, *ygh, *ygl, *Woh, *Wol;
    cudaGetSymbolAddress((void**)&xh,  g_x_h);  cudaGetSymbolAddress((void**)&xl,  g_x_l);
    cudaGetSymbolAddress((void**)&Wih, g_Wi_h); cudaGetSymbolAddress((void**)&Wil, g_Wi_l);
    cudaGetSymbolAddress((void**)&uh,  g_u_h);  cudaGetSymbolAddress((void**)&ul,  g_u_l);
    cudaGetSymbolAddress((void**)&Wxh, g_Wx_h); cudaGetSymbolAddress((void**)&Wxl, g_Wx_l);
    cudaGetSymbolAddress((void**)&dih, g_di_h); cudaGetSymbolAddress((void**)&dil, g_di_l);
    cudaGetSymbolAddress((void**)&Wdh, g_Wd_h); cudaGetSymbolAddress((void**)&Wdl, g_Wd_l);
    cudaGetSymbolAddress((void**)&ygh, g_yg_h); cudaGetSymbolAddress((void**)&ygl, g_yg_l);
    cudaGetSymbolAddress((void**)&Woh, g_Wo_h); cudaGetSymbolAddress((void**)&Wol, g_Wo_l);

    cudaFuncSetAttribute(gemm_mma<0>, cudaFuncAttributeMaxDynamicSharedMemorySize, GSMEM);
    cudaFuncSetAttribute(gemm_mma<1>, cudaFuncAttributeMaxDynamicSharedMemorySize, GSMEM);
    cudaFuncSetAttribute(gemm_mma<2>, cudaFuncAttributeMaxDynamicSharedMemorySize, GSMEM);
    cudaFuncSetAttribute(gemm_mma<3>, cudaFuncAttributeMaxDynamicSharedMemorySize, GSMEM);

    dim3 thr(256);
    dim3 thrg(512);

    // --- split conversions for static weights + x ---
    {
        size_t n;
        n = (size_t)MTOK * DM;
        split_bf16_kernel<<<cdiv_sz(n, 256), thr>>>(x, DM, DM, xh, xl, n);
        n = (size_t)2 * DI * DM;
        split_bf16_kernel<<<cdiv_sz(n, 256), thr>>>(W_in, DM, DM, Wih, Wil, n);
        n = (size_t)PROJW * DI;
        split_bf16_kernel<<<cdiv_sz(n, 256), thr>>>(W_x, DI, DI, Wxh, Wxl, n);
        n = (size_t)DI * DI;
        split_bf16_kernel<<<cdiv_sz(n, 256), thr>>>(W_dt, DI, DI, Wdh, Wdl, n);
        n = (size_t)DM * DI;
        split_bf16_kernel<<<cdiv_sz(n, 256), thr>>>(W_out, DI, DI, Woh, Wol, n);
    }

    // 1) xz = x @ W_in^T              (4096 x 4096, K=1024)
    gemm_mma<0><<<dim3((2 * DI) / BN, MTOK / BM), thrg, GSMEM>>>(
        xh, xl, Wih, Wil, xz, 2 * DI, MTOK, 2 * DI, DM, nullptr, nullptr, 0, nullptr, nullptr);

    // 2) u = silu(causal_conv(xs) + cb)   [+ fused hi/lo split]
    conv_silu_kernel<<<cdiv_sz((size_t)MTOK * DI, 256), thr>>>(conv_w, conv_b, uh, ul);

    // 3) proj = u @ W_x^T             (4096 x 2080, K=2048)  [+ fused d_in split]
    gemm_mma<3><<<dim3((PROJW + BN - 1) / BN, MTOK / BM), thrg, GSMEM>>>(
        uh, ul, Wxh, Wxl, proj, PROJW, MTOK, PROJW, DI, nullptr, nullptr, 0, dih, dil);

    // 4) delta = softplus(d_in @ W_dt^T + b_dt)
    gemm_mma<1><<<dim3(DI / BN, MTOK / BM), thrg, GSMEM>>>(
        dih, dil, Wdh, Wdl, dlt, DI, MTOK, DI, DI, b_dt, nullptr, 0, nullptr, nullptr);

    // 5) selective scan + skip + gate -> yg   [+ fused hi/lo split]
    scan_kernel<<<BATCHN * (DI / 16), thr>>>(A_log, Dp, ygh, ygl);

    // 6) out = yg @ W_out^T + x       (4096 x 1024, K=2048)
    gemm_mma<2><<<dim3(DM / BN, MTOK / BM), thrg, GSMEM>>>(
        ygh, ygl, Woh, Wol, out, DM, MTOK, DM, DI, nullptr, x, DM, nullptr, nullptr);

    // 7) layernorm in place
    layernorm_kernel<<<MTOK, thr>>>(out, ln_g, ln_b);
}

// round 17
// speedup vs baseline: 4.7048x; 1.6162x over previous
#include <cuda_runtime.h>
#include <cuda_fp16.h>
#include <math.h>
#include <cstdint>

// Problem constants
#define BATCHN 2
#define LEN    2048
#define DM     1024
#define DI     2048
#define DS     16
#define MTOK   (BATCHN*LEN)      // 4096 tokens
#define PROJW  (DI + 2*DS)       // 2080

__device__ __forceinline__ uint32_t smem_to_u32(const void* p) {
    uint32_t a;
    asm("{ .reg .u64 t; cvta.to.shared.u64 t, %1; cvt.u32.u64 %0, t; }" : "=r"(a) : "l"(p));
    return a;
}
#define SMEM_SWIZZLE_128B(byte_offset) \
    ((byte_offset) ^ (((byte_offset) >> 3) & 0x70))

#define LDMATRIX_X4(r0, r1, r2, r3, addr) \
    asm volatile("ldmatrix.sync.aligned.m8n8.x4.shared.b16 {%0,%1,%2,%3}, [%4];" \
        : "=r"(r0), "=r"(r1), "=r"(r2), "=r"(r3) : "r"(addr))
#define LDMATRIX_X2(r0, r1, addr) \
    asm volatile("ldmatrix.sync.aligned.m8n8.x2.shared.b16 {%0,%1}, [%2];" \
        : "=r"(r0), "=r"(r1) : "r"(addr))
#define MMA16816F16(d, a, b) \
    asm volatile("mma.sync.aligned.m16n8k16.row.col.f32.f16.f16.f32 " \
        "{%0,%1,%2,%3}, {%4,%5,%6,%7}, {%8,%9}, {%0,%1,%2,%3};" \
        : "+f"((d)[0]), "+f"((d)[1]), "+f"((d)[2]), "+f"((d)[3]) \
        : "r"((a)[0]), "r"((a)[1]), "r"((a)[2]), "r"((a)[3]), \
          "r"((b)[0]), "r"((b)[1]))

#define CP_ASYNC16(dst, src) \
    asm volatile("cp.async.cg.shared.global [%0], [%1], 16;" :: "r"(dst), "l"(src))
#define CP_ASYNC16_ZF(dst, src, sz) \
    asm volatile("cp.async.cg.shared.global [%0], [%1], 16, %2;" :: "r"(dst), "l"(src), "r"(sz))
#define CP_COMMIT() asm volatile("cp.async.commit_group;" ::: "memory")
#define CP_WAIT2()  asm volatile("cp.async.wait_group 2;" ::: "memory")
#define CP_WAIT1()  asm volatile("cp.async.wait_group 1;" ::: "memory")
#define CP_WAIT0()  asm volatile("cp.async.wait_group 0;" ::: "memory")

// ---------------- scratch (device globals; no allocation allowed) ----------------
__device__ float g_xz  [(size_t)MTOK * 2*DI];   // in_proj output [xs | z]
__device__ float g_u   [(size_t)MTOK * DI];     // conv+silu output (fp32, scan input)
__device__ float g_proj[(size_t)MTOK * PROJW];  // x_proj output [d_in | B | C]
__device__ float g_dlt [(size_t)MTOK * DI];     // softplus(dt)

// fp16 operand buffers
__device__ __half g_x_f  [(size_t)MTOK * DM];
__device__ __half g_Wi_f [(size_t)2*DI * DM];
__device__ __half g_u_f  [(size_t)MTOK * DI];
__device__ __half g_Wx_f [(size_t)PROJW * DI];
__device__ __half g_di_f [(size_t)MTOK * DI];
__device__ __half g_Wd_f [(size_t)DI * DI];
__device__ __half g_yg_f [(size_t)MTOK * DI];
__device__ __half g_Wo_f [(size_t)DM * DI];

// ---------------- float -> fp16 convert (contiguous) ----------------
__global__ void cvt_f16_kernel(const float* __restrict__ src,
                               __half* __restrict__ dst, size_t n)
{
    size_t idx = (size_t)blockIdx.x * blockDim.x + threadIdx.x;
    if (idx >= n) return;
    dst[idx] = __float2half(src[idx]);
}

// ---------------- HMMA fp16 GEMM, 512 threads, cp.async 3-stage pipeline ----------------
// BM=256, BN=128, BK=64. 16 warps each own 64x32 (wm 0..3, wn 0..3). SW128 smem + ldmatrix.
// Single-pass fp16 (fp32 accum). MODE 0: plain store; MODE 1: softplus(v+bias[n]);
// MODE 2: v+resid; MODE 3: store + fp16 convert of cols < DI
#define BM 256
#define BN 128
#define BK 64
#define ATILEB 32768              // 256 rows * 128 bytes
#define BTILEB 16384              // 128 rows * 128 bytes
#define STAGEB (ATILEB + BTILEB)  // A, B = 48 KB
#define NSTAGE 3
#define GSMEM (NSTAGE * STAGEB)   // 144 KB

template<int MODE>
__global__ void __launch_bounds__(512, 1)
gemm_mma(const __half* __restrict__ A, const __half* __restrict__ B,
         float* __restrict__ C, int ldc, int M, int N, int K,
         const float* __restrict__ bias,
         const float* __restrict__ resid, int ldr,
         __half* __restrict__ of)
{
    extern __shared__ char smbuf[];
    const uint32_t usm = smem_to_u32(smbuf);

    const int tid  = threadIdx.x;
    const int lane = tid & 31;
    const int warp = tid >> 5;      // 0..15
    const int wm   = warp >> 2;     // 0..3  (64-row band)
    const int wn   = warp & 3;      // 0..3  (32-col band)
    const int m0   = blockIdx.y * BM;
    const int n0   = blockIdx.x * BN;

    float acc[4][4][4];
#pragma unroll
    for (int i = 0; i < 4; i++)
#pragma unroll
        for (int j = 0; j < 4; j++)
#pragma unroll
            for (int q = 0; q < 4; q++) acc[i][j][q] = 0.f;

    // per-thread load coords
    // A: 2048 16B-units per tile; 512 thr * 4 units
    const int lrA = tid >> 1;                // 0..255 (row)
    const int lcA = (tid & 1) * 4;           // 0 or 4
    // B: 1024 16B-units per tile; 512 thr * 2 units
    const int lrB = tid >> 2;                // 0..127 (row)
    const int lcB = (tid & 3) * 2;           // 0,2,4,6
    const bool bvalid = (n0 + lrB) < N;
    const uint32_t bsz = bvalid ? 16u : 0u;
    const size_t aoff = (size_t)(m0 + lrA) * K;
    const size_t boff = (size_t)(bvalid ? (n0 + lrB) : 0) * K;

    // ldmatrix per-lane offsets
    const int a_row = wm * 64 + (lane & 15);
    const int a_ku  = lane >> 4;
    const int b_row = wn * 32 + (lane & 7);
    const int b_ku  = (lane >> 3) & 1;

    const int nch = K / BK;

    // ---- stage loader ----
    auto load_stage = [&](int ci, int s) {
        const uint32_t st = usm + s * STAGEB;
        const int k0 = ci * BK;
#pragma unroll
        for (int q = 0; q < 4; q++) {
            const int c = lcA + q;
            const uint32_t so = SMEM_SWIZZLE_128B((uint32_t)(lrA * 128 + c * 16));
            CP_ASYNC16(st + so, A + aoff + (size_t)(k0 + c * 8));
        }
#pragma unroll
        for (int q = 0; q < 2; q++) {
            const int c = lcB + q;
            const uint32_t so = SMEM_SWIZZLE_128B((uint32_t)(lrB * 128 + c * 16));
            CP_ASYNC16_ZF(st + ATILEB + so, B + boff + (size_t)(k0 + c * 8), bsz);
        }
        CP_COMMIT();
    };

    // prologue: fill stages 0 and 1
    load_stage(0, 0);
    if (nch > 1) load_stage(1, 1);

    for (int i = 0; i < nch; i++) {
        if (i + 2 < nch)       { load_stage(i + 2, (i + 2) % NSTAGE); CP_WAIT2(); }
        else if (i + 2 == nch) { CP_WAIT1(); }
        else                   { CP_WAIT0(); }
        __syncthreads();

        const uint32_t st = usm + (i % NSTAGE) * STAGEB;
        const uint32_t uA = st;
        const uint32_t uB = st + ATILEB;

#pragma unroll
        for (int kk = 0; kk < 4; kk++) {
            const int aun = kk * 2 + a_ku;
            const int bun = kk * 2 + b_ku;
            uint32_t bh[4][2];
#pragma unroll
            for (int ni = 0; ni < 4; ni++) {
                const uint32_t off =
                    SMEM_SWIZZLE_128B((uint32_t)((b_row + ni * 8) * 128 + bun * 16));
                LDMATRIX_X2(bh[ni][0], bh[ni][1], uB + off);
            }
#pragma unroll
            for (int mi = 0; mi < 4; mi++) {
                const uint32_t off =
                    SMEM_SWIZZLE_128B((uint32_t)((a_row + mi * 16) * 128 + aun * 16));
                uint32_t ah[4];
                LDMATRIX_X4(ah[0], ah[1], ah[2], ah[3], uA + off);
#pragma unroll
                for (int ni = 0; ni < 4; ni++) {
                    MMA16816F16(acc[mi][ni], ah, bh[ni]);
                }
            }
        }
        __syncthreads();
    }

    // epilogue
#pragma unroll
    for (int mi = 0; mi < 4; mi++) {
#pragma unroll
        for (int ni = 0; ni < 4; ni++) {
            const int m = m0 + wm * 64 + mi * 16 + (lane >> 2);
            const int n = n0 + wn * 32 + ni * 8 + (lane & 3) * 2;
            if (n < N) {
#pragma unroll
                for (int h = 0; h < 2; h++) {
                    const int mm = m + h * 8;
                    float v0 = acc[mi][ni][h * 2 + 0];
                    float v1 = acc[mi][ni][h * 2 + 1];
                    if (MODE == 1) {
                        v0 += bias[n];     v1 += bias[n + 1];
                        v0 = (v0 > 20.f) ? v0 : log1pf(expf(v0));
                        v1 = (v1 > 20.f) ? v1 : log1pf(expf(v1));
                    }
                    if (MODE == 2) {
                        const float2 rr = *(const float2*)(resid + (size_t)mm * ldr + n);
                        v0 += rr.x; v1 += rr.y;
                    }
                    *(float2*)(C + (size_t)mm * ldc + n) = make_float2(v0, v1);
                    if (MODE == 3 && n < DI) {
                        const size_t o = (size_t)mm * DI + n;
                        of[o]     = __float2half(v0);
                        of[o + 1] = __float2half(v1);
                    }
                }
            }
        }
    }
}

// ---------------- depthwise causal conv1d (k=4) + SiLU, fused fp16 convert ----------------
__global__ void conv_silu_kernel(const float* __restrict__ cw,
                                 const float* __restrict__ cb,
                                 __half* __restrict__ uf)
{
    const size_t idx = (size_t)blockIdx.x * blockDim.x + threadIdx.x;
    if (idx >= (size_t)MTOK * DI) return;
    const int d = (int)(idx % DI);
    const int m = (int)(idx / DI);
    const int t = m % LEN;

    const float w0 = cw[d * 4 + 0], w1 = cw[d * 4 + 1];
    const float w2 = cw[d * 4 + 2], w3 = cw[d * 4 + 3];
    float acc = cb[d];
    if (t >= 3) acc = fmaf(g_xz[(size_t)(m - 3) * (2 * DI) + d], w0, acc);
    if (t >= 2) acc = fmaf(g_xz[(size_t)(m - 2) * (2 * DI) + d], w1, acc);
    if (t >= 1) acc = fmaf(g_xz[(size_t)(m - 1) * (2 * DI) + d], w2, acc);
    acc = fmaf(g_xz[(size_t)m * (2 * DI) + d], w3, acc);
    const float sg = 1.f / (1.f + expf(-acc));
    const float uv = acc * sg;
    g_u[idx] = uv;
    uf[idx] = __float2half(uv);
}

// ---------------- selective scan + skip + gate, windowed prefetch, fp16 out ----------------
#define SW 8
__global__ __launch_bounds__(256)
void scan_kernel(const float* __restrict__ A_log,
                 const float* __restrict__ Dp,
                 __half* __restrict__ ygf)
{
    const int tid  = threadIdx.x;
    const int wid  = tid >> 5;
    const int lane = tid & 31;
    const int hh   = lane >> 4;        // which channel within warp
    const int n    = lane & 15;

    const int blocks_per_batch = DI / 16;
    const int b      = blockIdx.x / blocks_per_batch;
    const int dchunk = blockIdx.x % blocks_per_batch;
    const int d      = dchunk * 16 + wid * 2 + hh;

    const float a_coef = -expf(A_log[d * DS + n]);
    const float Dd     = Dp[d];
    float s = 0.f;

    const int mbase = b * LEN;
    for (int t0 = 0; t0 < LEN; t0 += SW) {
        float dt8[SW], uu8[SW], Bv8[SW], Cv8[SW], zz8[SW];
#pragma unroll
        for (int j = 0; j < SW; j++) {
            const int m = mbase + t0 + j;
            dt8[j] = g_dlt[(size_t)m * DI + d];
            uu8[j] = g_u  [(size_t)m * DI + d];
            Bv8[j] = g_proj[(size_t)m * PROJW + DI + n];
            Cv8[j] = g_proj[(size_t)m * PROJW + DI + DS + n];
            zz8[j] = g_xz[(size_t)m * (2 * DI) + DI + d];
        }
#pragma unroll
        for (int j = 0; j < SW; j++) {
            const float dA = __expf(dt8[j] * a_coef);
            s = fmaf(s, dA, dt8[j] * Bv8[j] * uu8[j]);

            float p = s * Cv8[j];
            p += __shfl_xor_sync(0xffffffffu, p, 8);
            p += __shfl_xor_sync(0xffffffffu, p, 4);
            p += __shfl_xor_sync(0xffffffffu, p, 2);
            p += __shfl_xor_sync(0xffffffffu, p, 1);

            if (n == 0) {
                const float y  = p + uu8[j] * Dd;
                const float sz = zz8[j] / (1.f + __expf(-zz8[j]));
                const float yv = y * sz;
                ygf[(size_t)(mbase + t0 + j) * DI + d] = __float2half(yv);
            }
        }
    }
}

// ---------------- LayerNorm over last dim (1024), in-place on d_out ----------------
__global__ __launch_bounds__(256)
void layernorm_kernel(float* __restrict__ out,
                      const float* __restrict__ g,
                      const float* __restrict__ bta)
{
    const int m = blockIdx.x;
    const int tid = threadIdx.x;
    float* row = out + (size_t)m * DM;

    float4 v = ((const float4*)row)[tid];
    const float4 gg = ((const float4*)g)[tid];
    const float4 bb = ((const float4*)bta)[tid];

    __shared__ float sh[8];
    __shared__ float bc;

    float sv = v.x + v.y + v.z + v.w;
    for (int o = 16; o > 0; o >>= 1) sv += __shfl_xor_sync(0xffffffffu, sv, o);
    if ((tid & 31) == 0) sh[tid >> 5] = sv;
    __syncthreads();
    if (tid < 32) {
        float t2 = (tid < 8) ? sh[tid] : 0.f;
        for (int o = 4; o > 0; o >>= 1) t2 += __shfl_xor_sync(0xffffffffu, t2, o);
        if (tid == 0) bc = t2;
    }
    __syncthreads();
    const float mu = bc * (1.f / DM);
    __syncthreads();

    float dx0 = v.x - mu, dx1 = v.y - mu, dx2 = v.z - mu, dx3 = v.w - mu;
    float sq = dx0 * dx0 + dx1 * dx1 + dx2 * dx2 + dx3 * dx3;
    for (int o = 16; o > 0; o >>= 1) sq += __shfl_xor_sync(0xffffffffu, sq, o);
    if ((tid & 31) == 0) sh[tid >> 5] = sq;
    __syncthreads();
    if (tid < 32) {
        float t2 = (tid < 8) ? sh[tid] : 0.f;
        for (int o = 4; o > 0; o >>= 1) t2 += __shfl_xor_sync(0xffffffffu, t2, o);
        if (tid == 0) bc = t2;
    }
    __syncthreads();
    const float var = bc * (1.f / DM);
    const float inv = rsqrtf(var + 1e-5f);

    v.x = dx0 * inv * gg.x + bb.x;
    v.y = dx1 * inv * gg.y + bb.y;
    v.z = dx2 * inv * gg.z + bb.z;
    v.w = dx3 * inv * gg.w + bb.w;
    ((float4*)row)[tid] = v;
}

// ---------------- host launch ----------------
static inline unsigned cdiv_sz(size_t a, size_t b) { return (unsigned)((a + b - 1) / b); }

extern "C" void kernel_launch(void* const* d_in, const int* in_sizes, int n_in,
                              void* d_out, int out_size)
{
    const float* x      = (const float*)d_in[0];
    const float* W_in   = (const float*)d_in[1];
    const float* conv_w = (const float*)d_in[2];
    const float* conv_b = (const float*)d_in[3];
    const float* W_x    = (const float*)d_in[4];
    const float* W_dt   = (const float*)d_in[5];
    const float* b_dt   = (const float*)d_in[6];
    const float* A_log  = (const float*)d_in[7];
    const float* Dp     = (const float*)d_in[8];
    const float* W_out  = (const float*)d_in[9];
    const float* ln_g   = (const float*)d_in[10];
    const float* ln_b   = (const float*)d_in[11];
    float* out = (float*)d_out;

    float *xz, *u, *proj, *dlt;
    cudaGetSymbolAddress((void**)&xz,   g_xz);
    cudaGetSymbolAddress((void**)&u,    g_u);
    cudaGetSymbolAddress((void**)&proj, g_proj);
    cudaGetSymbolAddress((void**)&dlt,  g_dlt);

    __half *xf, *Wif, *uf, *Wxf, *dif, *Wdf, *ygf, *Wof;
    cudaGetSymbolAddress((void**)&xf,  g_x_f);
    cudaGetSymbolAddress((void**)&Wif, g_Wi_f);
    cudaGetSymbolAddress((void**)&uf,  g_u_f);
    cudaGetSymbolAddress((void**)&Wxf, g_Wx_f);
    cudaGetSymbolAddress((void**)&dif, g_di_f);
    cudaGetSymbolAddress((void**)&Wdf, g_Wd_f);
    cudaGetSymbolAddress((void**)&ygf, g_yg_f);
    cudaGetSymbolAddress((void**)&Wof, g_Wo_f);

    cudaFuncSetAttribute(gemm_mma<0>, cudaFuncAttributeMaxDynamicSharedMemorySize, GSMEM);
    cudaFuncSetAttribute(gemm_mma<1>, cudaFuncAttributeMaxDynamicSharedMemorySize, GSMEM);
    cudaFuncSetAttribute(gemm_mma<2>, cudaFuncAttributeMaxDynamicSharedMemorySize, GSMEM);
    cudaFuncSetAttribute(gemm_mma<3>, cudaFuncAttributeMaxDynamicSharedMemorySize, GSMEM);

    dim3 thr(256);
    dim3 thrg(512);

    // --- fp16 conversions for static weights + x (all contiguous) ---
    {
        size_t n;
        n = (size_t)MTOK * DM;
        cvt_f16_kernel<<<cdiv_sz(n, 256), thr>>>(x, xf, n);
        n = (size_t)2 * DI * DM;
        cvt_f16_kernel<<<cdiv_sz(n, 256), thr>>>(W_in, Wif, n);
        n = (size_t)PROJW * DI;
        cvt_f16_kernel<<<cdiv_sz(n, 256), thr>>>(W_x, Wxf, n);
        n = (size_t)DI * DI;
        cvt_f16_kernel<<<cdiv_sz(n, 256), thr>>>(W_dt, Wdf, n);
        n = (size_t)DM * DI;
        cvt_f16_kernel<<<cdiv_sz(n, 256), thr>>>(W_out, Wof, n);
    }

    // 1) xz = x @ W_in^T              (4096 x 4096, K=1024)
    gemm_mma<0><<<dim3((2 * DI) / BN, MTOK / BM), thrg, GSMEM>>>(
        xf, Wif, xz, 2 * DI, MTOK, 2 * DI, DM, nullptr, nullptr, 0, nullptr);

    // 2) u = silu(causal_conv(xs) + cb)   [+ fused fp16 convert]
    conv_silu_kernel<<<cdiv_sz((size_t)MTOK * DI, 256), thr>>>(conv_w, conv_b, uf);

    // 3) proj = u @ W_x^T             (4096 x 2080, K=2048)  [+ fused d_in convert]
    gemm_mma<3><<<dim3((PROJW + BN - 1) / BN, MTOK / BM), thrg, GSMEM>>>(
        uf, Wxf, proj, PROJW, MTOK, PROJW, DI, nullptr, nullptr, 0, dif);

    // 4) delta = softplus(d_in @ W_dt^T + b_dt)
    gemm_mma<1><<<dim3(DI / BN, MTOK / BM), thrg, GSMEM>>>(
        dif, Wdf, dlt, DI, MTOK, DI, DI, b_dt, nullptr, 0, nullptr);

    // 5) selective scan + skip + gate -> ygf (fp16)
    scan_kernel<<<BATCHN * (DI / 16), thr>>>(A_log, Dp, ygf);

    // 6) out = yg @ W_out^T + x       (4096 x 1024, K=2048)
    gemm_mma<2><<<dim3(DM / BN, MTOK / BM), thrg, GSMEM>>>(
        ygf, Wof, out, DM, MTOK, DM, DI, nullptr, x, DM, nullptr);

    // 7) layernorm in place
    layernorm_kernel<<<MTOK, thr>>>(out, ln_g, ln_b);
}